// round 6
// baseline (speedup 1.0000x reference)
#include <cuda_runtime.h>
#include <cuda_bf16.h>
#include <cstdint>

#define B_   8
#define V_   256
#define T_   64

// ---------------------------------------------------------------------------
// Global scratch
// ---------------------------------------------------------------------------
__device__ __nv_bfloat16 g_xh[8ll * 256 * 64 * 256];     // [b][v][t][256ic]
__device__ __nv_bfloat16 g_xl[8ll * 256 * 64 * 256];
__device__ __nv_bfloat16 g_qkvh[8ll * 64 * 256 * 192];   // [b][t][v][192]
__device__ __nv_bfloat16 g_qkvl[8ll * 64 * 256 * 192];
__device__ __nv_bfloat16 g_avh[8ll * 256 * 64 * 128];    // [b][v][t][128ic]
__device__ __nv_bfloat16 g_avl[8ll * 256 * 64 * 128];
__device__ __nv_bfloat16 g_w1h[192 * 2304], g_w1l[192 * 2304];  // [oc][chunk][tap][16]
__device__ __nv_bfloat16 g_w2h[256 * 1152], g_w2l[256 * 1152];

// ---------------------------------------------------------------------------
// Helpers
// ---------------------------------------------------------------------------
__device__ __forceinline__ uint32_t smem_u32(const void* p) {
    return (uint32_t)__cvta_generic_to_shared(p);
}
__device__ __forceinline__ uint32_t pack2bf(float f0, float f1) {
    __nv_bfloat162 h = __floats2bfloat162_rn(f0, f1);   // .x=f0 (low 16)
    return *(uint32_t*)&h;
}
__device__ __forceinline__ void split2(float f0, float f1,
                                       uint32_t& hp, uint32_t& lp) {
    hp = pack2bf(f0, f1);
    float h0 = __uint_as_float(hp << 16);
    float h1 = __uint_as_float(hp & 0xFFFF0000u);
    lp = pack2bf(f0 - h0, f1 - h1);
}

#define LDMX4(r, a) \
    asm volatile("ldmatrix.sync.aligned.m8n8.x4.shared.b16 {%0,%1,%2,%3},[%4];" \
        : "=r"((r)[0]), "=r"((r)[1]), "=r"((r)[2]), "=r"((r)[3]) : "r"(a))
#define LDMX4T(r, a) \
    asm volatile("ldmatrix.sync.aligned.m8n8.x4.trans.shared.b16 {%0,%1,%2,%3},[%4];" \
        : "=r"((r)[0]), "=r"((r)[1]), "=r"((r)[2]), "=r"((r)[3]) : "r"(a))
#define CP16(dst, src, sz) \
    asm volatile("cp.async.cg.shared.global [%0], [%1], 16, %2;" \
                 :: "r"(dst), "l"(src), "r"(sz) : "memory")
#define CP_COMMIT() asm volatile("cp.async.commit_group;" ::: "memory")
#define CP_WAIT(n)  asm volatile("cp.async.wait_group %0;" :: "n"(n) : "memory")

__device__ __forceinline__ void mma16816(float* c, const uint32_t* a, const uint32_t* b) {
    asm volatile(
        "mma.sync.aligned.m16n8k16.row.col.f32.bf16.bf16.f32 "
        "{%0,%1,%2,%3},{%4,%5,%6,%7},{%8,%9},{%0,%1,%2,%3};"
        : "+f"(c[0]), "+f"(c[1]), "+f"(c[2]), "+f"(c[3])
        : "r"(a[0]), "r"(a[1]), "r"(a[2]), "r"(a[3]), "r"(b[0]), "r"(b[1]));
}

// ---------------------------------------------------------------------------
// split_x: x NCHW fp32 -> [b][y][t][256ic] bf16 hi/lo
// ---------------------------------------------------------------------------
__global__ void split_x_k(const float* __restrict__ x,
                          __nv_bfloat16* __restrict__ xh,
                          __nv_bfloat16* __restrict__ xl) {
    extern __shared__ float s[];               // [256 ic][65]
    const int y = blockIdx.x, b = blockIdx.y, tid = threadIdx.x;
    for (int r = 0; r < 64; r++) {
        int idx = r * 256 + tid, ic = idx >> 6, t = idx & 63;
        s[ic * 65 + t] = x[(((size_t)b * 256 + ic) * 256 + y) * 64 + t];
    }
    __syncthreads();
    size_t ob = ((size_t)(b * 256 + y)) * 64 * 256;
    for (int r = 0; r < 32; r++) {
        int idx = r * 512 + tid * 2, t = idx >> 8, ic = idx & 255;
        float f0 = s[ic * 65 + t], f1 = s[(ic + 1) * 65 + t];
        uint32_t hp, lp;
        split2(f0, f1, hp, lp);
        *(uint32_t*)(xh + ob + (size_t)t * 256 + ic) = hp;
        *(uint32_t*)(xl + ob + (size_t)t * 256 + ic) = lp;
    }
}

// ---------------------------------------------------------------------------
// Weight packing: w[oc][ic][3][3] -> [oc][icchunk][tap][16ic] hi/lo
// ---------------------------------------------------------------------------
__global__ void pack_w1_k(const float* __restrict__ wq,
                          const float* __restrict__ wk,
                          const float* __restrict__ wv) {
    int id = blockIdx.x * blockDim.x + threadIdx.x;
    if (id >= 192 * 2304) return;
    int oc = id / 2304, kp = id % 2304;
    int chunk = kp / 144, rem = kp % 144, tap = rem / 16, i = rem & 15;
    int ic = chunk * 16 + i;
    float v;
    if (oc < 32)       v = wq[(oc * 256 + ic) * 9 + tap];
    else if (oc < 64)  v = wk[((oc - 32) * 256 + ic) * 9 + tap];
    else               v = wv[((oc - 64) * 256 + ic) * 9 + tap];
    __nv_bfloat16 h = __float2bfloat16(v);
    g_w1h[id] = h;
    g_w1l[id] = __float2bfloat16(v - __bfloat162float(h));
}

__global__ void pack_w2_k(const float* __restrict__ wo) {
    int id = blockIdx.x * blockDim.x + threadIdx.x;
    if (id >= 256 * 1152) return;
    int oc = id / 1152, kp = id % 1152;
    int chunk = kp / 144, rem = kp % 144, tap = rem / 16, i = rem & 15;
    int ic = chunk * 16 + i;
    float v = wo[(oc * 128 + ic) * 9 + tap];
    __nv_bfloat16 h = __float2bfloat16(v);
    g_w2h[id] = h;
    g_w2l[id] = __float2bfloat16(v - __bfloat162float(h));
}

// ---------------------------------------------------------------------------
// conv3x3 via mma.sync bf16 (hi/lo split, 3 passes), cp.async double-buffered.
// CTA: 512 thr (16 warps: 8 m-warps x 2 n-warps). M=512 positions
// (8 V-rows x 64 T) x N=64 oc. Chunk = 16 ic.
// Patch: [10 rows][68 cols] pixels of 48B. B: [64 oc][304B: 9 taps x 16 ic].
// Inner loop: pass-major over mt-pairs (dep distance 8); B hi/lo fused LDMX4.
// ---------------------------------------------------------------------------
#define A_LO   32640
#define B_HI   65280
#define BUFSZ  104192
#define CONV_SMEM 208384

template<int ICC, int OCTOT, bool TRANS>
__global__ __launch_bounds__(512, 1)
void conv_mma(const __nv_bfloat16* __restrict__ inh,
              const __nv_bfloat16* __restrict__ inl,
              const __nv_bfloat16* __restrict__ wh,
              const __nv_bfloat16* __restrict__ wl,
              __nv_bfloat16* __restrict__ outh,
              __nv_bfloat16* __restrict__ outl,
              float* __restrict__ out32,
              const float* __restrict__ resid,
              const float* __restrict__ sigma) {
    constexpr int IC = ICC * 16;
    extern __shared__ char sm[];

    const int tid  = threadIdx.x;
    const int lane = tid & 31;
    const int w    = tid >> 5;
    const int ocB  = blockIdx.x * 64;
    const int y0   = blockIdx.y * 8;
    const int b    = blockIdx.z;
    const int m0   = (w & 7) * 64;
    const int n0   = (w >> 3) * 32;
    const uint32_t su = smem_u32(sm);

    float acc[4][4][4];
#pragma unroll
    for (int i = 0; i < 4; i++)
#pragma unroll
        for (int j = 0; j < 4; j++)
#pragma unroll
            for (int e = 0; e < 4; e++) acc[i][j][e] = 0.f;

    auto stage = [&](int c, int buf) {
        uint32_t sdu = su + buf * BUFSZ;
        // A patch: 10x66 pixels, 32B (16 ic) each, hi+lo
        for (int i = tid; i < 1320; i += 512) {
            int half = i & 1, p = i >> 1;
            int row = p / 66, col = p - row * 66;
            int gy = y0 + row - 1, gt = col - 1;
            bool ok = ((unsigned)gy < 256u) && ((unsigned)gt < 64u);
            const __nv_bfloat16* base = half ? inl : inh;
            const __nv_bfloat16* src = ok
                ? base + ((size_t)((b * 256 + gy) * 64 + gt)) * IC + c * 16
                : base;
            uint32_t dst = sdu + half * A_LO + (uint32_t)(row * 68 + col) * 48;
            int sz = ok ? 16 : 0;
            CP16(dst, src, sz);
            CP16(dst + 16, src + 8, sz);
        }
        // B: 64 oc x 144 bf16 (9 taps x 16 ic), hi+lo
        for (int i = tid; i < 2304; i += 512) {
            int half = i >= 1152;
            int r = half ? i - 1152 : i;
            int n = r / 18, seg = r - n * 18;
            const __nv_bfloat16* src = (half ? wl : wh)
                + ((size_t)(ocB + n) * ICC + c) * 144 + seg * 8;
            uint32_t dst = sdu + B_HI + half * 19456 + n * 304 + seg * 16;
            CP16(dst, src, 16);
        }
        CP_COMMIT();
    };

    stage(0, 0);

    const int l16 = lane & 15;
    const int l8  = lane & 7;
    const uint32_t bhalf = ((lane >> 3) & 1) * 16 + (lane >> 4) * 19456;

    for (int c = 0; c < ICC; ++c) {
        if (c + 1 < ICC) { stage(c + 1, (c + 1) & 1); CP_WAIT(1); }
        else             { CP_WAIT(0); }
        __syncthreads();

        const uint32_t sa = su + (c & 1) * BUFSZ;
        const uint32_t sb = sa + B_HI;
#pragma unroll
        for (int tap = 0; tap < 9; ++tap) {
            const int ky = tap / 3, kx = tap - ky * 3;
            // B fragments: one LDMX4 per nt fetches hi(2 frags)+lo(2 frags)
            uint32_t bf[4][4];
#pragma unroll
            for (int nt = 0; nt < 4; ++nt) {
                uint32_t ad = sb + (n0 + nt * 8 + l8) * 304 + tap * 32 + bhalf;
                LDMX4(bf[nt], ad);
            }
#pragma unroll
            for (int mp = 0; mp < 2; ++mp) {
                uint32_t a0h[4], a0l[4], a1h[4], a1l[4];
                {
                    int mrow = m0 + (2 * mp) * 16 + l16;
                    int rp = (mrow >> 6) + ky, cp = (mrow & 63) + kx;
                    uint32_t ad = sa + (uint32_t)(rp * 68 + cp) * 48 + (lane >> 4) * 16;
                    LDMX4(a0h, ad);
                    LDMX4(a0l, ad + A_LO);
                }
                {
                    int mrow = m0 + (2 * mp + 1) * 16 + l16;
                    int rp = (mrow >> 6) + ky, cp = (mrow & 63) + kx;
                    uint32_t ad = sa + (uint32_t)(rp * 68 + cp) * 48 + (lane >> 4) * 16;
                    LDMX4(a1h, ad);
                    LDMX4(a1l, ad + A_LO);
                }
                // pass-major: dependency distance 8
#pragma unroll
                for (int nt = 0; nt < 4; ++nt) mma16816(acc[2 * mp][nt],     a0h, &bf[nt][0]);
#pragma unroll
                for (int nt = 0; nt < 4; ++nt) mma16816(acc[2 * mp + 1][nt], a1h, &bf[nt][0]);
#pragma unroll
                for (int nt = 0; nt < 4; ++nt) mma16816(acc[2 * mp][nt],     a0h, &bf[nt][2]);
#pragma unroll
                for (int nt = 0; nt < 4; ++nt) mma16816(acc[2 * mp + 1][nt], a1h, &bf[nt][2]);
#pragma unroll
                for (int nt = 0; nt < 4; ++nt) mma16816(acc[2 * mp][nt],     a0l, &bf[nt][0]);
#pragma unroll
                for (int nt = 0; nt < 4; ++nt) mma16816(acc[2 * mp + 1][nt], a1l, &bf[nt][0]);
            }
        }
        __syncthreads();
    }

    // ---- epilogue ----
    const int r0l = lane >> 2, c0l = (lane & 3) * 2;
    if constexpr (TRANS) {
#pragma unroll
        for (int mt = 0; mt < 4; ++mt)
#pragma unroll
            for (int nt = 0; nt < 4; ++nt) {
                int oc = ocB + n0 + nt * 8 + c0l;
#pragma unroll
                for (int h = 0; h < 2; ++h) {
                    int m = m0 + mt * 16 + r0l + h * 8;
                    int v = y0 + (m >> 6), t = m & 63;
                    uint32_t hp, lp;
                    split2(acc[mt][nt][h * 2], acc[mt][nt][h * 2 + 1], hp, lp);
                    size_t base = ((size_t)((b * 64 + t) * 256 + v)) * OCTOT + oc;
                    *(uint32_t*)(outh + base) = hp;
                    *(uint32_t*)(outl + base) = lp;
                }
            }
    } else {
        float sg = sigma[0];
#pragma unroll
        for (int mt = 0; mt < 4; ++mt)
#pragma unroll
            for (int nt = 0; nt < 4; ++nt)
#pragma unroll
                for (int h = 0; h < 2; ++h) {
                    int m = m0 + mt * 16 + r0l + h * 8;
                    int v = y0 + (m >> 6), t = m & 63;
#pragma unroll
                    for (int e = 0; e < 2; ++e) {
                        int oc = ocB + n0 + nt * 8 + c0l + e;
                        size_t idx = (((size_t)b * OCTOT + oc) * 256 + v) * 64 + t;
                        out32[idx] = resid[idx] + sg * acc[mt][nt][h * 2 + e];
                    }
                }
    }
}

// ---------------------------------------------------------------------------
// Attention via mma.sync bf16 hi/lo (flash-style online softmax).
// One CTA per (b,t): 512 thr, 16 warps, warp owns 16 query rows.
// SMEM: Q hi/lo [256 x 80B], K hi/lo [256 x 80B], V hi/lo [256 x 272B].
// 4 key chunks of 64.  Output: split bf16 [b][v][t][128].
// Pass-major MMA ordering over ntp-pairs (dep distance 4).
// ---------------------------------------------------------------------------
#define QH_O 0
#define QL_O 20480
#define KH_O 40960
#define KL_O 61440
#define VH_O 81920
#define VL_O 151552
#define ATTN_SMEM 221184

__global__ __launch_bounds__(512, 1)
void attn_kernel(const __nv_bfloat16* __restrict__ qh,
                 const __nv_bfloat16* __restrict__ ql,
                 __nv_bfloat16* __restrict__ avh,
                 __nv_bfloat16* __restrict__ avl) {
    extern __shared__ char smc[];
    const int tid  = threadIdx.x;
    const int lane = tid & 31;
    const int w    = tid >> 5;
    const int t    = blockIdx.x;
    const int b    = blockIdx.y;
    const uint32_t su = smem_u32(smc);

    // ---- load slice [256 rows][192 ch] hi+lo into Q/K/V smem ----
    const size_t sbase = ((size_t)(b * 64 + t)) * 256 * 192;
    for (int idx = tid; idx < 12288; idx += 512) {
        int half = idx >= 6144;
        int r = half ? idx - 6144 : idx;
        int row = r / 24, seg = r - row * 24;
        float4 val = *(const float4*)((half ? ql : qh) + sbase + (size_t)row * 192 + seg * 8);
        uint32_t dst;
        if (seg < 4)       dst = (half ? QL_O : QH_O) + row * 80 + seg * 16;
        else if (seg < 8)  dst = (half ? KL_O : KH_O) + row * 80 + (seg - 4) * 16;
        else               dst = (half ? VL_O : VH_O) + row * 272 + (seg - 8) * 16;
        *(float4*)(smc + dst) = val;
    }
    __syncthreads();

    const int q0  = w * 16;
    const int l16 = lane & 15;

    float o[16][4];
#pragma unroll
    for (int i = 0; i < 16; i++)
#pragma unroll
        for (int j = 0; j < 4; j++) o[i][j] = 0.f;
    float mrow[2] = {-1e30f, -1e30f};
    float lrow[2] = {0.f, 0.f};

    for (int c0 = 0; c0 < 4; ++c0) {
        // ---- S = Q K^T (chunk of 64 keys), 3-pass hi/lo, pass-major ----
        float s[8][4];
#pragma unroll
        for (int i = 0; i < 8; i++)
#pragma unroll
            for (int j = 0; j < 4; j++) s[i][j] = 0.f;

#pragma unroll
        for (int kk = 0; kk < 2; ++kk) {
            uint32_t aH[4], aL[4];
            uint32_t qa = su + QH_O + (q0 + l16) * 80 + (lane >> 4) * 16 + kk * 32;
            LDMX4(aH, qa);
            LDMX4(aL, qa + (QL_O - QH_O));
#pragma unroll
            for (int np = 0; np < 2; ++np) {
                uint32_t kh0[4], kl0[4], kh1[4], kl1[4];
                uint32_t ka0 = su + KH_O + (c0 * 64 + (2 * np) * 16 + l16) * 80
                             + (lane >> 4) * 16 + kk * 32;
                LDMX4(kh0, ka0);
                LDMX4(kl0, ka0 + (KL_O - KH_O));
                LDMX4(kh1, ka0 + 16 * 80);
                LDMX4(kl1, ka0 + 16 * 80 + (KL_O - KH_O));
                uint32_t b0h[2] = {kh0[0], kh0[2]}, b1h[2] = {kh0[1], kh0[3]};
                uint32_t b2h[2] = {kh1[0], kh1[2]}, b3h[2] = {kh1[1], kh1[3]};
                uint32_t b0l[2] = {kl0[0], kl0[2]}, b1l[2] = {kl0[1], kl0[3]};
                uint32_t b2l[2] = {kl1[0], kl1[2]}, b3l[2] = {kl1[1], kl1[3]};
                float* s0 = s[4 * np]; float* s1 = s[4 * np + 1];
                float* s2 = s[4 * np + 2]; float* s3 = s[4 * np + 3];
                mma16816(s0, aH, b0h); mma16816(s1, aH, b1h);
                mma16816(s2, aH, b2h); mma16816(s3, aH, b3h);
                mma16816(s0, aL, b0h); mma16816(s1, aL, b1h);
                mma16816(s2, aL, b2h); mma16816(s3, aL, b3h);
                mma16816(s0, aH, b0l); mma16816(s1, aH, b1l);
                mma16816(s2, aH, b2l); mma16816(s3, aH, b3l);
            }
        }

        // ---- online softmax update ----
#pragma unroll
        for (int h = 0; h < 2; ++h) {
            float mc = -1e30f;
#pragma unroll
            for (int nt = 0; nt < 8; ++nt)
                mc = fmaxf(mc, fmaxf(s[nt][2 * h], s[nt][2 * h + 1]));
            mc = fmaxf(mc, __shfl_xor_sync(0xffffffffu, mc, 1));
            mc = fmaxf(mc, __shfl_xor_sync(0xffffffffu, mc, 2));
            float mn = fmaxf(mrow[h], mc);
            float sc = __expf(mrow[h] - mn);
            mrow[h] = mn;
            float ls = 0.f;
#pragma unroll
            for (int nt = 0; nt < 8; ++nt) {
                float p0 = __expf(s[nt][2 * h] - mn);
                float p1 = __expf(s[nt][2 * h + 1] - mn);
                s[nt][2 * h] = p0; s[nt][2 * h + 1] = p1;
                ls += p0 + p1;
            }
            ls += __shfl_xor_sync(0xffffffffu, ls, 1);
            ls += __shfl_xor_sync(0xffffffffu, ls, 2);
            lrow[h] = lrow[h] * sc + ls;
#pragma unroll
            for (int nt = 0; nt < 16; ++nt) {
                o[nt][2 * h]     *= sc;
                o[nt][2 * h + 1] *= sc;
            }
        }

        // ---- O += P V (3-pass hi/lo), pass-major over ntp-pairs ----
#pragma unroll
        for (int kk = 0; kk < 4; ++kk) {
            uint32_t ph[4], pl[4];
            split2(s[2 * kk][0],     s[2 * kk][1],     ph[0], pl[0]);
            split2(s[2 * kk][2],     s[2 * kk][3],     ph[1], pl[1]);
            split2(s[2 * kk + 1][0], s[2 * kk + 1][1], ph[2], pl[2]);
            split2(s[2 * kk + 1][2], s[2 * kk + 1][3], ph[3], pl[3]);
#pragma unroll
            for (int np = 0; np < 4; ++np) {
                uint32_t vh0[4], vl0[4], vh1[4], vl1[4];
                uint32_t va = su + VH_O + (c0 * 64 + kk * 16 + l16) * 272
                            + (lane >> 4) * 16 + (2 * np) * 32;
                LDMX4T(vh0, va);
                LDMX4T(vl0, va + (VL_O - VH_O));
                LDMX4T(vh1, va + 32);
                LDMX4T(vl1, va + 32 + (VL_O - VH_O));
                uint32_t bh0[2] = {vh0[0], vh0[1]}, bh1[2] = {vh0[2], vh0[3]};
                uint32_t bh2[2] = {vh1[0], vh1[1]}, bh3[2] = {vh1[2], vh1[3]};
                uint32_t bl0[2] = {vl0[0], vl0[1]}, bl1[2] = {vl0[2], vl0[3]};
                uint32_t bl2[2] = {vl1[0], vl1[1]}, bl3[2] = {vl1[2], vl1[3]};
                float* o0 = o[4 * np]; float* o1 = o[4 * np + 1];
                float* o2 = o[4 * np + 2]; float* o3 = o[4 * np + 3];
                mma16816(o0, ph, bh0); mma16816(o1, ph, bh1);
                mma16816(o2, ph, bh2); mma16816(o3, ph, bh3);
                mma16816(o0, pl, bh0); mma16816(o1, pl, bh1);
                mma16816(o2, pl, bh2); mma16816(o3, pl, bh3);
                mma16816(o0, ph, bl0); mma16816(o1, ph, bl1);
                mma16816(o2, ph, bl2); mma16816(o3, ph, bl3);
            }
        }
    }

    // ---- epilogue: normalize, split bf16, store [b][v][t][128] ----
    float rin[2] = {1.f / lrow[0], 1.f / lrow[1]};
#pragma unroll
    for (int nt = 0; nt < 16; ++nt) {
        int ch = nt * 8 + (lane & 3) * 2;
#pragma unroll
        for (int h = 0; h < 2; ++h) {
            int v = q0 + (lane >> 2) + h * 8;
            float f0 = o[nt][2 * h] * rin[h];
            float f1 = o[nt][2 * h + 1] * rin[h];
            uint32_t hp, lp;
            split2(f0, f1, hp, lp);
            size_t ad = ((size_t)(b * 256 + v) * 64 + t) * 128 + ch;
            *(uint32_t*)(avh + ad) = hp;
            *(uint32_t*)(avl + ad) = lp;
        }
    }
}

// ---------------------------------------------------------------------------
extern "C" void kernel_launch(void* const* d_in, const int* in_sizes, int n_in,
                              void* d_out, int out_size) {
    const float* x     = (const float*)d_in[0];
    const float* wq    = (const float*)d_in[1];
    const float* wk    = (const float*)d_in[2];
    const float* wv    = (const float*)d_in[3];
    const float* wo    = (const float*)d_in[4];
    const float* sigma = (const float*)d_in[5];
    float* out = (float*)d_out;

    __nv_bfloat16 *xh, *xl, *qkvh, *qkvl, *avh, *avl, *w1h, *w1l, *w2h, *w2l;
    cudaGetSymbolAddress((void**)&xh,   g_xh);
    cudaGetSymbolAddress((void**)&xl,   g_xl);
    cudaGetSymbolAddress((void**)&qkvh, g_qkvh);
    cudaGetSymbolAddress((void**)&qkvl, g_qkvl);
    cudaGetSymbolAddress((void**)&avh,  g_avh);
    cudaGetSymbolAddress((void**)&avl,  g_avl);
    cudaGetSymbolAddress((void**)&w1h,  g_w1h);
    cudaGetSymbolAddress((void**)&w1l,  g_w1l);
    cudaGetSymbolAddress((void**)&w2h,  g_w2h);
    cudaGetSymbolAddress((void**)&w2l,  g_w2l);

    cudaFuncSetAttribute(split_x_k,
                         cudaFuncAttributeMaxDynamicSharedMemorySize, 66560);
    split_x_k<<<dim3(256, 8), 256, 66560>>>(x, xh, xl);

    pack_w1_k<<<(192 * 2304 + 255) / 256, 256>>>(wq, wk, wv);
    pack_w2_k<<<(256 * 1152 + 255) / 256, 256>>>(wo);

    {   // conv1: IC=256 (16 chunks), OCTOT=192, split-bf16 transposed output
        auto k = conv_mma<16, 192, true>;
        cudaFuncSetAttribute(k, cudaFuncAttributeMaxDynamicSharedMemorySize,
                             CONV_SMEM);
        k<<<dim3(3, 32, 8), 512, CONV_SMEM>>>(xh, xl, w1h, w1l,
                                              qkvh, qkvl, nullptr, nullptr, nullptr);
    }

    cudaFuncSetAttribute(attn_kernel,
                         cudaFuncAttributeMaxDynamicSharedMemorySize, ATTN_SMEM);
    attn_kernel<<<dim3(T_, B_), 512, ATTN_SMEM>>>(qkvh, qkvl, avh, avl);

    {   // conv2: IC=128 (8 chunks), OCTOT=256, fp32 out + residual
        auto k = conv_mma<8, 256, false>;
        cudaFuncSetAttribute(k, cudaFuncAttributeMaxDynamicSharedMemorySize,
                             CONV_SMEM);
        k<<<dim3(4, 32, 8), 512, CONV_SMEM>>>(avh, avl, w2h, w2l,
                                              nullptr, nullptr, out, x, sigma);
    }
}

// round 8
// speedup vs baseline: 1.0880x; 1.0880x over previous
#include <cuda_runtime.h>
#include <cuda_bf16.h>
#include <cstdint>

#define B_   8
#define V_   256
#define T_   64

// ---------------------------------------------------------------------------
// Global scratch
// ---------------------------------------------------------------------------
__device__ __nv_bfloat16 g_xh[8ll * 256 * 64 * 256];     // [b][v][t][256ic]
__device__ __nv_bfloat16 g_xl[8ll * 256 * 64 * 256];
__device__ __nv_bfloat16 g_qkvh[8ll * 64 * 256 * 192];   // [b][t][v][192]
__device__ __nv_bfloat16 g_qkvl[8ll * 64 * 256 * 192];
__device__ __nv_bfloat16 g_avh[8ll * 256 * 64 * 128];    // [b][v][t][128ic]
__device__ __nv_bfloat16 g_avl[8ll * 256 * 64 * 128];
__device__ __nv_bfloat16 g_w1h[192 * 2304], g_w1l[192 * 2304];  // [oc][chunk][tap][16]
__device__ __nv_bfloat16 g_w2h[256 * 1152], g_w2l[256 * 1152];

// ---------------------------------------------------------------------------
// Helpers
// ---------------------------------------------------------------------------
__device__ __forceinline__ uint32_t smem_u32(const void* p) {
    return (uint32_t)__cvta_generic_to_shared(p);
}
__device__ __forceinline__ uint32_t pack2bf(float f0, float f1) {
    __nv_bfloat162 h = __floats2bfloat162_rn(f0, f1);   // .x=f0 (low 16)
    return *(uint32_t*)&h;
}
__device__ __forceinline__ void split2(float f0, float f1,
                                       uint32_t& hp, uint32_t& lp) {
    hp = pack2bf(f0, f1);
    float h0 = __uint_as_float(hp << 16);
    float h1 = __uint_as_float(hp & 0xFFFF0000u);
    lp = pack2bf(f0 - h0, f1 - h1);
}

#define LDMX4(r, a) \
    asm volatile("ldmatrix.sync.aligned.m8n8.x4.shared.b16 {%0,%1,%2,%3},[%4];" \
        : "=r"((r)[0]), "=r"((r)[1]), "=r"((r)[2]), "=r"((r)[3]) : "r"(a))
#define LDMX4T(r, a) \
    asm volatile("ldmatrix.sync.aligned.m8n8.x4.trans.shared.b16 {%0,%1,%2,%3},[%4];" \
        : "=r"((r)[0]), "=r"((r)[1]), "=r"((r)[2]), "=r"((r)[3]) : "r"(a))
#define CP16(dst, src, sz) \
    asm volatile("cp.async.cg.shared.global [%0], [%1], 16, %2;" \
                 :: "r"(dst), "l"(src), "r"(sz) : "memory")
#define CP_COMMIT() asm volatile("cp.async.commit_group;" ::: "memory")
#define CP_WAIT(n)  asm volatile("cp.async.wait_group %0;" :: "n"(n) : "memory")

__device__ __forceinline__ void mma16816(float* c, const uint32_t* a, const uint32_t* b) {
    asm volatile(
        "mma.sync.aligned.m16n8k16.row.col.f32.bf16.bf16.f32 "
        "{%0,%1,%2,%3},{%4,%5,%6,%7},{%8,%9},{%0,%1,%2,%3};"
        : "+f"(c[0]), "+f"(c[1]), "+f"(c[2]), "+f"(c[3])
        : "r"(a[0]), "r"(a[1]), "r"(a[2]), "r"(a[3]), "r"(b[0]), "r"(b[1]));
}

// ---------------------------------------------------------------------------
// split_x: x NCHW fp32 -> [b][y][t][256ic] bf16 hi/lo
// ---------------------------------------------------------------------------
__global__ void split_x_k(const float* __restrict__ x,
                          __nv_bfloat16* __restrict__ xh,
                          __nv_bfloat16* __restrict__ xl) {
    extern __shared__ float s[];               // [256 ic][65]
    const int y = blockIdx.x, b = blockIdx.y, tid = threadIdx.x;
    for (int r = 0; r < 64; r++) {
        int idx = r * 256 + tid, ic = idx >> 6, t = idx & 63;
        s[ic * 65 + t] = x[(((size_t)b * 256 + ic) * 256 + y) * 64 + t];
    }
    __syncthreads();
    size_t ob = ((size_t)(b * 256 + y)) * 64 * 256;
    for (int r = 0; r < 32; r++) {
        int idx = r * 512 + tid * 2, t = idx >> 8, ic = idx & 255;
        float f0 = s[ic * 65 + t], f1 = s[(ic + 1) * 65 + t];
        uint32_t hp, lp;
        split2(f0, f1, hp, lp);
        *(uint32_t*)(xh + ob + (size_t)t * 256 + ic) = hp;
        *(uint32_t*)(xl + ob + (size_t)t * 256 + ic) = lp;
    }
}

// ---------------------------------------------------------------------------
// Weight packing: w[oc][ic][3][3] -> [oc][icchunk][tap][16ic] hi/lo
// ---------------------------------------------------------------------------
__global__ void pack_w1_k(const float* __restrict__ wq,
                          const float* __restrict__ wk,
                          const float* __restrict__ wv) {
    int id = blockIdx.x * blockDim.x + threadIdx.x;
    if (id >= 192 * 2304) return;
    int oc = id / 2304, kp = id % 2304;
    int chunk = kp / 144, rem = kp % 144, tap = rem / 16, i = rem & 15;
    int ic = chunk * 16 + i;
    float v;
    if (oc < 32)       v = wq[(oc * 256 + ic) * 9 + tap];
    else if (oc < 64)  v = wk[((oc - 32) * 256 + ic) * 9 + tap];
    else               v = wv[((oc - 64) * 256 + ic) * 9 + tap];
    __nv_bfloat16 h = __float2bfloat16(v);
    g_w1h[id] = h;
    g_w1l[id] = __float2bfloat16(v - __bfloat162float(h));
}

__global__ void pack_w2_k(const float* __restrict__ wo) {
    int id = blockIdx.x * blockDim.x + threadIdx.x;
    if (id >= 256 * 1152) return;
    int oc = id / 1152, kp = id % 1152;
    int chunk = kp / 144, rem = kp % 144, tap = rem / 16, i = rem & 15;
    int ic = chunk * 16 + i;
    float v = wo[(oc * 128 + ic) * 9 + tap];
    __nv_bfloat16 h = __float2bfloat16(v);
    g_w2h[id] = h;
    g_w2l[id] = __float2bfloat16(v - __bfloat162float(h));
}

// ---------------------------------------------------------------------------
// conv3x3 via mma.sync bf16 (hi/lo split, 3 passes).
// CTA: 256 thr (8 warps: 4 m x 2 n), 2 CTAs/SM. M=256 positions
// (4 V-rows x 64 T) x N=64 oc. Chunk = 16 ic.
// A double-buffered (cp.async), B single-buffered.
// Patch: [6 rows][66 cols] pixels of 48B stride (32B payload), hi/lo regions.
// B: [64 oc][304B stride: 9 taps x 16 ic], hi/lo regions.
// All smem strides are multiples of 16B (cp.async/ldmatrix alignment).
// Commit scheme per chunk c: group(B_c), group(A_{c+1}), CP_WAIT(1)
//   -> B_c and A_c complete, A_{c+1} in flight.
// ---------------------------------------------------------------------------
#define A_LO    19008          // lo offset within one A buffer (6*66*48)
#define A_BUF   38016          // one A buffer (hi+lo)
#define BH_O    76032          // B hi base (2*A_BUF)
#define B_LO    19456          // B lo offset from BH_O (64*304)
#define CONV_SMEM 114944       // BH_O + 2*B_LO

template<int ICC, int OCTOT, bool TRANS>
__global__ __launch_bounds__(256, 2)
void conv_mma(const __nv_bfloat16* __restrict__ inh,
              const __nv_bfloat16* __restrict__ inl,
              const __nv_bfloat16* __restrict__ wh,
              const __nv_bfloat16* __restrict__ wl,
              __nv_bfloat16* __restrict__ outh,
              __nv_bfloat16* __restrict__ outl,
              float* __restrict__ out32,
              const float* __restrict__ resid,
              const float* __restrict__ sigma) {
    constexpr int IC = ICC * 16;
    extern __shared__ char sm[];

    const int tid  = threadIdx.x;
    const int lane = tid & 31;
    const int w    = tid >> 5;
    const int ocB  = blockIdx.x * 64;
    const int y0   = blockIdx.y * 4;
    const int b    = blockIdx.z;
    const int m0   = (w & 3) * 64;
    const int n0   = (w >> 2) * 32;
    const uint32_t su = smem_u32(sm);

    float acc[4][4][4];
#pragma unroll
    for (int i = 0; i < 4; i++)
#pragma unroll
        for (int j = 0; j < 4; j++)
#pragma unroll
            for (int e = 0; e < 4; e++) acc[i][j][e] = 0.f;

    // stage A patch for chunk c into buffer buf: 6x66 pixels, hi+lo (32B each)
    auto stageA = [&](int c, int buf) {
        uint32_t au = su + buf * A_BUF;
        for (int i = tid; i < 792; i += 256) {
            int half = i & 1, p = i >> 1;
            int row = p / 66, col = p - row * 66;
            int gy = y0 + row - 1, gt = col - 1;
            bool ok = ((unsigned)gy < 256u) && ((unsigned)gt < 64u);
            const __nv_bfloat16* base = half ? inl : inh;
            const __nv_bfloat16* src = ok
                ? base + ((size_t)((b * 256 + gy) * 64 + gt)) * IC + c * 16
                : base;
            uint32_t dst = au + half * A_LO + (uint32_t)(row * 66 + col) * 48;
            int sz = ok ? 16 : 0;
            CP16(dst, src, sz);
            CP16(dst + 16, src + 8, sz);
        }
    };
    // stage B for chunk c (single buffer): 64 oc x 18 segs of 16B, hi+lo
    auto stageB = [&](int c) {
        for (int i = tid; i < 2304; i += 256) {
            int half = i >= 1152;
            int r = half ? i - 1152 : i;
            int n = r / 18, seg = r - n * 18;
            const __nv_bfloat16* src = (half ? wl : wh)
                + ((size_t)(ocB + n) * ICC + c) * 144 + seg * 8;
            uint32_t dst = su + BH_O + half * B_LO + n * 304 + seg * 16;
            CP16(dst, src, 16);
        }
    };

    stageA(0, 0);
    CP_COMMIT();

    const int l16 = lane & 15;
    const int l8  = lane & 7;
    const uint32_t bhalf = ((lane >> 3) & 1) * 16 + (lane >> 4) * B_LO;

    for (int c = 0; c < ICC; ++c) {
        stageB(c);
        CP_COMMIT();
        if (c + 1 < ICC) stageA(c + 1, (c + 1) & 1);
        CP_COMMIT();
        CP_WAIT(1);            // B(c) + A(c) complete; A(c+1) in flight
        __syncthreads();

        const uint32_t sa = su + (c & 1) * A_BUF;
        const uint32_t sb = su + BH_O;
#pragma unroll
        for (int tap = 0; tap < 9; ++tap) {
            const int ky = tap / 3, kx = tap - ky * 3;
            // B fragments: one LDMX4 per nt fetches hi(2 frags)+lo(2 frags)
            uint32_t bf[4][4];
#pragma unroll
            for (int nt = 0; nt < 4; ++nt) {
                uint32_t ad = sb + (n0 + nt * 8 + l8) * 304 + tap * 32 + bhalf;
                LDMX4(bf[nt], ad);
            }
#pragma unroll
            for (int mp = 0; mp < 2; ++mp) {
                uint32_t a0h[4], a0l[4], a1h[4], a1l[4];
                {
                    int mrow = m0 + (2 * mp) * 16 + l16;
                    int rp = (mrow >> 6) + ky, cp = (mrow & 63) + kx;
                    uint32_t ad = sa + (uint32_t)(rp * 66 + cp) * 48 + (lane >> 4) * 16;
                    LDMX4(a0h, ad);
                    LDMX4(a0l, ad + A_LO);
                }
                {
                    int mrow = m0 + (2 * mp + 1) * 16 + l16;
                    int rp = (mrow >> 6) + ky, cp = (mrow & 63) + kx;
                    uint32_t ad = sa + (uint32_t)(rp * 66 + cp) * 48 + (lane >> 4) * 16;
                    LDMX4(a1h, ad);
                    LDMX4(a1l, ad + A_LO);
                }
                // pass-major: dependency distance 8
#pragma unroll
                for (int nt = 0; nt < 4; ++nt) mma16816(acc[2 * mp][nt],     a0h, &bf[nt][0]);
#pragma unroll
                for (int nt = 0; nt < 4; ++nt) mma16816(acc[2 * mp + 1][nt], a1h, &bf[nt][0]);
#pragma unroll
                for (int nt = 0; nt < 4; ++nt) mma16816(acc[2 * mp][nt],     a0h, &bf[nt][2]);
#pragma unroll
                for (int nt = 0; nt < 4; ++nt) mma16816(acc[2 * mp + 1][nt], a1h, &bf[nt][2]);
#pragma unroll
                for (int nt = 0; nt < 4; ++nt) mma16816(acc[2 * mp][nt],     a0l, &bf[nt][0]);
#pragma unroll
                for (int nt = 0; nt < 4; ++nt) mma16816(acc[2 * mp + 1][nt], a1l, &bf[nt][0]);
            }
        }
        __syncthreads();       // protect B buffer + A buffer reuse
    }

    // ---- epilogue ----
    const int r0l = lane >> 2, c0l = (lane & 3) * 2;
    if constexpr (TRANS) {
#pragma unroll
        for (int mt = 0; mt < 4; ++mt)
#pragma unroll
            for (int nt = 0; nt < 4; ++nt) {
                int oc = ocB + n0 + nt * 8 + c0l;
#pragma unroll
                for (int h = 0; h < 2; ++h) {
                    int m = m0 + mt * 16 + r0l + h * 8;
                    int v = y0 + (m >> 6), t = m & 63;
                    uint32_t hp, lp;
                    split2(acc[mt][nt][h * 2], acc[mt][nt][h * 2 + 1], hp, lp);
                    size_t base = ((size_t)((b * 64 + t) * 256 + v)) * OCTOT + oc;
                    *(uint32_t*)(outh + base) = hp;
                    *(uint32_t*)(outl + base) = lp;
                }
            }
    } else {
        float sg = sigma[0];
#pragma unroll
        for (int mt = 0; mt < 4; ++mt)
#pragma unroll
            for (int nt = 0; nt < 4; ++nt)
#pragma unroll
                for (int h = 0; h < 2; ++h) {
                    int m = m0 + mt * 16 + r0l + h * 8;
                    int v = y0 + (m >> 6), t = m & 63;
#pragma unroll
                    for (int e = 0; e < 2; ++e) {
                        int oc = ocB + n0 + nt * 8 + c0l + e;
                        size_t idx = (((size_t)b * OCTOT + oc) * 256 + v) * 64 + t;
                        out32[idx] = resid[idx] + sg * acc[mt][nt][h * 2 + e];
                    }
                }
    }
}

// ---------------------------------------------------------------------------
// Attention via mma.sync bf16 hi/lo (flash-style online softmax).
// One CTA per (b,t): 512 thr, 16 warps, warp owns 16 query rows.
// SMEM: Q hi/lo [256 x 80B], K hi/lo [256 x 80B], V hi/lo [256 x 272B].
// 4 key chunks of 64.  Output: split bf16 [b][v][t][128].
// ---------------------------------------------------------------------------
#define QH_O 0
#define QL_O 20480
#define KH_O 40960
#define KL_O 61440
#define VH_O 81920
#define VL_O 151552
#define ATTN_SMEM 221184

__global__ __launch_bounds__(512, 1)
void attn_kernel(const __nv_bfloat16* __restrict__ qh,
                 const __nv_bfloat16* __restrict__ ql,
                 __nv_bfloat16* __restrict__ avh,
                 __nv_bfloat16* __restrict__ avl) {
    extern __shared__ char smc[];
    const int tid  = threadIdx.x;
    const int lane = tid & 31;
    const int w    = tid >> 5;
    const int t    = blockIdx.x;
    const int b    = blockIdx.y;
    const uint32_t su = smem_u32(smc);

    // ---- load slice [256 rows][192 ch] hi+lo into Q/K/V smem ----
    const size_t sbase = ((size_t)(b * 64 + t)) * 256 * 192;
    for (int idx = tid; idx < 12288; idx += 512) {
        int half = idx >= 6144;
        int r = half ? idx - 6144 : idx;
        int row = r / 24, seg = r - row * 24;
        float4 val = *(const float4*)((half ? ql : qh) + sbase + (size_t)row * 192 + seg * 8);
        uint32_t dst;
        if (seg < 4)       dst = (half ? QL_O : QH_O) + row * 80 + seg * 16;
        else if (seg < 8)  dst = (half ? KL_O : KH_O) + row * 80 + (seg - 4) * 16;
        else               dst = (half ? VL_O : VH_O) + row * 272 + (seg - 8) * 16;
        *(float4*)(smc + dst) = val;
    }
    __syncthreads();

    const int q0  = w * 16;
    const int l16 = lane & 15;

    float o[16][4];
#pragma unroll
    for (int i = 0; i < 16; i++)
#pragma unroll
        for (int j = 0; j < 4; j++) o[i][j] = 0.f;
    float mrow[2] = {-1e30f, -1e30f};
    float lrow[2] = {0.f, 0.f};

    for (int c0 = 0; c0 < 4; ++c0) {
        // ---- S = Q K^T (chunk of 64 keys), 3-pass hi/lo, pass-major ----
        float s[8][4];
#pragma unroll
        for (int i = 0; i < 8; i++)
#pragma unroll
            for (int j = 0; j < 4; j++) s[i][j] = 0.f;

#pragma unroll
        for (int kk = 0; kk < 2; ++kk) {
            uint32_t aH[4], aL[4];
            uint32_t qa = su + QH_O + (q0 + l16) * 80 + (lane >> 4) * 16 + kk * 32;
            LDMX4(aH, qa);
            LDMX4(aL, qa + (QL_O - QH_O));
#pragma unroll
            for (int np = 0; np < 2; ++np) {
                uint32_t kh0[4], kl0[4], kh1[4], kl1[4];
                uint32_t ka0 = su + KH_O + (c0 * 64 + (2 * np) * 16 + l16) * 80
                             + (lane >> 4) * 16 + kk * 32;
                LDMX4(kh0, ka0);
                LDMX4(kl0, ka0 + (KL_O - KH_O));
                LDMX4(kh1, ka0 + 16 * 80);
                LDMX4(kl1, ka0 + 16 * 80 + (KL_O - KH_O));
                uint32_t b0h[2] = {kh0[0], kh0[2]}, b1h[2] = {kh0[1], kh0[3]};
                uint32_t b2h[2] = {kh1[0], kh1[2]}, b3h[2] = {kh1[1], kh1[3]};
                uint32_t b0l[2] = {kl0[0], kl0[2]}, b1l[2] = {kl0[1], kl0[3]};
                uint32_t b2l[2] = {kl1[0], kl1[2]}, b3l[2] = {kl1[1], kl1[3]};
                float* s0 = s[4 * np]; float* s1 = s[4 * np + 1];
                float* s2 = s[4 * np + 2]; float* s3 = s[4 * np + 3];
                mma16816(s0, aH, b0h); mma16816(s1, aH, b1h);
                mma16816(s2, aH, b2h); mma16816(s3, aH, b3h);
                mma16816(s0, aL, b0h); mma16816(s1, aL, b1h);
                mma16816(s2, aL, b2h); mma16816(s3, aL, b3h);
                mma16816(s0, aH, b0l); mma16816(s1, aH, b1l);
                mma16816(s2, aH, b2l); mma16816(s3, aH, b3l);
            }
        }

        // ---- online softmax update ----
#pragma unroll
        for (int h = 0; h < 2; ++h) {
            float mc = -1e30f;
#pragma unroll
            for (int nt = 0; nt < 8; ++nt)
                mc = fmaxf(mc, fmaxf(s[nt][2 * h], s[nt][2 * h + 1]));
            mc = fmaxf(mc, __shfl_xor_sync(0xffffffffu, mc, 1));
            mc = fmaxf(mc, __shfl_xor_sync(0xffffffffu, mc, 2));
            float mn = fmaxf(mrow[h], mc);
            float sc = __expf(mrow[h] - mn);
            mrow[h] = mn;
            float ls = 0.f;
#pragma unroll
            for (int nt = 0; nt < 8; ++nt) {
                float p0 = __expf(s[nt][2 * h] - mn);
                float p1 = __expf(s[nt][2 * h + 1] - mn);
                s[nt][2 * h] = p0; s[nt][2 * h + 1] = p1;
                ls += p0 + p1;
            }
            ls += __shfl_xor_sync(0xffffffffu, ls, 1);
            ls += __shfl_xor_sync(0xffffffffu, ls, 2);
            lrow[h] = lrow[h] * sc + ls;
#pragma unroll
            for (int nt = 0; nt < 16; ++nt) {
                o[nt][2 * h]     *= sc;
                o[nt][2 * h + 1] *= sc;
            }
        }

        // ---- O += P V (3-pass hi/lo), pass-major over ntp-pairs ----
#pragma unroll
        for (int kk = 0; kk < 4; ++kk) {
            uint32_t ph[4], pl[4];
            split2(s[2 * kk][0],     s[2 * kk][1],     ph[0], pl[0]);
            split2(s[2 * kk][2],     s[2 * kk][3],     ph[1], pl[1]);
            split2(s[2 * kk + 1][0], s[2 * kk + 1][1], ph[2], pl[2]);
            split2(s[2 * kk + 1][2], s[2 * kk + 1][3], ph[3], pl[3]);
#pragma unroll
            for (int np = 0; np < 4; ++np) {
                uint32_t vh0[4], vl0[4], vh1[4], vl1[4];
                uint32_t va = su + VH_O + (c0 * 64 + kk * 16 + l16) * 272
                            + (lane >> 4) * 16 + (2 * np) * 32;
                LDMX4T(vh0, va);
                LDMX4T(vl0, va + (VL_O - VH_O));
                LDMX4T(vh1, va + 32);
                LDMX4T(vl1, va + 32 + (VL_O - VH_O));
                uint32_t bh0[2] = {vh0[0], vh0[1]}, bh1[2] = {vh0[2], vh0[3]};
                uint32_t bh2[2] = {vh1[0], vh1[1]}, bh3[2] = {vh1[2], vh1[3]};
                uint32_t bl0[2] = {vl0[0], vl0[1]}, bl1[2] = {vl0[2], vl0[3]};
                uint32_t bl2[2] = {vl1[0], vl1[1]}, bl3[2] = {vl1[2], vl1[3]};
                float* o0 = o[4 * np]; float* o1 = o[4 * np + 1];
                float* o2 = o[4 * np + 2]; float* o3 = o[4 * np + 3];
                mma16816(o0, ph, bh0); mma16816(o1, ph, bh1);
                mma16816(o2, ph, bh2); mma16816(o3, ph, bh3);
                mma16816(o0, pl, bh0); mma16816(o1, pl, bh1);
                mma16816(o2, pl, bh2); mma16816(o3, pl, bh3);
                mma16816(o0, ph, bl0); mma16816(o1, ph, bl1);
                mma16816(o2, ph, bl2); mma16816(o3, ph, bl3);
            }
        }
    }

    // ---- epilogue: normalize, split bf16, store [b][v][t][128] ----
    float rin[2] = {1.f / lrow[0], 1.f / lrow[1]};
#pragma unroll
    for (int nt = 0; nt < 16; ++nt) {
        int ch = nt * 8 + (lane & 3) * 2;
#pragma unroll
        for (int h = 0; h < 2; ++h) {
            int v = q0 + (lane >> 2) + h * 8;
            float f0 = o[nt][2 * h] * rin[h];
            float f1 = o[nt][2 * h + 1] * rin[h];
            uint32_t hp, lp;
            split2(f0, f1, hp, lp);
            size_t ad = ((size_t)(b * 256 + v) * 64 + t) * 128 + ch;
            *(uint32_t*)(avh + ad) = hp;
            *(uint32_t*)(avl + ad) = lp;
        }
    }
}

// ---------------------------------------------------------------------------
extern "C" void kernel_launch(void* const* d_in, const int* in_sizes, int n_in,
                              void* d_out, int out_size) {
    const float* x     = (const float*)d_in[0];
    const float* wq    = (const float*)d_in[1];
    const float* wk    = (const float*)d_in[2];
    const float* wv    = (const float*)d_in[3];
    const float* wo    = (const float*)d_in[4];
    const float* sigma = (const float*)d_in[5];
    float* out = (float*)d_out;

    __nv_bfloat16 *xh, *xl, *qkvh, *qkvl, *avh, *avl, *w1h, *w1l, *w2h, *w2l;
    cudaGetSymbolAddress((void**)&xh,   g_xh);
    cudaGetSymbolAddress((void**)&xl,   g_xl);
    cudaGetSymbolAddress((void**)&qkvh, g_qkvh);
    cudaGetSymbolAddress((void**)&qkvl, g_qkvl);
    cudaGetSymbolAddress((void**)&avh,  g_avh);
    cudaGetSymbolAddress((void**)&avl,  g_avl);
    cudaGetSymbolAddress((void**)&w1h,  g_w1h);
    cudaGetSymbolAddress((void**)&w1l,  g_w1l);
    cudaGetSymbolAddress((void**)&w2h,  g_w2h);
    cudaGetSymbolAddress((void**)&w2l,  g_w2l);

    cudaFuncSetAttribute(split_x_k,
                         cudaFuncAttributeMaxDynamicSharedMemorySize, 66560);
    split_x_k<<<dim3(256, 8), 256, 66560>>>(x, xh, xl);

    pack_w1_k<<<(192 * 2304 + 255) / 256, 256>>>(wq, wk, wv);
    pack_w2_k<<<(256 * 1152 + 255) / 256, 256>>>(wo);

    {   // conv1: IC=256 (16 chunks), OCTOT=192, split-bf16 transposed output
        auto k = conv_mma<16, 192, true>;
        cudaFuncSetAttribute(k, cudaFuncAttributeMaxDynamicSharedMemorySize,
                             CONV_SMEM);
        k<<<dim3(3, 64, 8), 256, CONV_SMEM>>>(xh, xl, w1h, w1l,
                                              qkvh, qkvl, nullptr, nullptr, nullptr);
    }

    cudaFuncSetAttribute(attn_kernel,
                         cudaFuncAttributeMaxDynamicSharedMemorySize, ATTN_SMEM);
    attn_kernel<<<dim3(T_, B_), 512, ATTN_SMEM>>>(qkvh, qkvl, avh, avl);

    {   // conv2: IC=128 (8 chunks), OCTOT=256, fp32 out + residual
        auto k = conv_mma<8, 256, false>;
        cudaFuncSetAttribute(k, cudaFuncAttributeMaxDynamicSharedMemorySize,
                             CONV_SMEM);
        k<<<dim3(4, 64, 8), 256, CONV_SMEM>>>(avh, avl, w2h, w2l,
                                              nullptr, nullptr, out, x, sigma);
    }
}

// round 9
// speedup vs baseline: 1.4416x; 1.3249x over previous
#include <cuda_runtime.h>
#include <cuda_bf16.h>
#include <cuda_fp16.h>
#include <cstdint>

#define B_   8
#define V_   256
#define T_   64

// ---------------------------------------------------------------------------
// Global scratch
// ---------------------------------------------------------------------------
__device__ __half g_xh[8ll * 256 * 64 * 256];            // [b][v][t][256ic] fp16
__device__ __half g_xl[8ll * 256 * 64 * 256];
__device__ __nv_bfloat16 g_qkvh[8ll * 64 * 256 * 192];   // [b][t][v][192] bf16
__device__ __nv_bfloat16 g_qkvl[8ll * 64 * 256 * 192];
__device__ __half g_avh[8ll * 256 * 64 * 128];           // [b][v][t][128ic] fp16
__device__ __half g_avl[8ll * 256 * 64 * 128];
__device__ __half g_w1h[192 * 2304];                     // [oc][chunk][tap][16] fp16
__device__ __half g_w2h[256 * 1152];

// ---------------------------------------------------------------------------
// Helpers
// ---------------------------------------------------------------------------
__device__ __forceinline__ uint32_t smem_u32(const void* p) {
    return (uint32_t)__cvta_generic_to_shared(p);
}
__device__ __forceinline__ uint32_t pack2bf(float f0, float f1) {
    __nv_bfloat162 h = __floats2bfloat162_rn(f0, f1);
    return *(uint32_t*)&h;
}
__device__ __forceinline__ void split2(float f0, float f1,
                                       uint32_t& hp, uint32_t& lp) {
    hp = pack2bf(f0, f1);
    float h0 = __uint_as_float(hp << 16);
    float h1 = __uint_as_float(hp & 0xFFFF0000u);
    lp = pack2bf(f0 - h0, f1 - h1);
}
__device__ __forceinline__ void split2h(float f0, float f1,
                                        uint32_t& hp, uint32_t& lp) {
    __half2 h = __floats2half2_rn(f0, f1);
    hp = *(uint32_t*)&h;
    float r0 = f0 - __half2float(__low2half(h));
    float r1 = f1 - __half2float(__high2half(h));
    __half2 l = __floats2half2_rn(r0, r1);
    lp = *(uint32_t*)&l;
}

#define LDMX4(r, a) \
    asm volatile("ldmatrix.sync.aligned.m8n8.x4.shared.b16 {%0,%1,%2,%3},[%4];" \
        : "=r"((r)[0]), "=r"((r)[1]), "=r"((r)[2]), "=r"((r)[3]) : "r"(a))
#define LDMX4T(r, a) \
    asm volatile("ldmatrix.sync.aligned.m8n8.x4.trans.shared.b16 {%0,%1,%2,%3},[%4];" \
        : "=r"((r)[0]), "=r"((r)[1]), "=r"((r)[2]), "=r"((r)[3]) : "r"(a))
#define CP16(dst, src, sz) \
    asm volatile("cp.async.cg.shared.global [%0], [%1], 16, %2;" \
                 :: "r"(dst), "l"(src), "r"(sz) : "memory")
#define CP_COMMIT() asm volatile("cp.async.commit_group;" ::: "memory")
#define CP_WAIT(n)  asm volatile("cp.async.wait_group %0;" :: "n"(n) : "memory")

__device__ __forceinline__ void mma16816(float* c, const uint32_t* a, const uint32_t* b) {
    asm volatile(
        "mma.sync.aligned.m16n8k16.row.col.f32.bf16.bf16.f32 "
        "{%0,%1,%2,%3},{%4,%5,%6,%7},{%8,%9},{%0,%1,%2,%3};"
        : "+f"(c[0]), "+f"(c[1]), "+f"(c[2]), "+f"(c[3])
        : "r"(a[0]), "r"(a[1]), "r"(a[2]), "r"(a[3]), "r"(b[0]), "r"(b[1]));
}
__device__ __forceinline__ void mma16816h(float* c, const uint32_t* a, const uint32_t* b) {
    asm volatile(
        "mma.sync.aligned.m16n8k16.row.col.f32.f16.f16.f32 "
        "{%0,%1,%2,%3},{%4,%5,%6,%7},{%8,%9},{%0,%1,%2,%3};"
        : "+f"(c[0]), "+f"(c[1]), "+f"(c[2]), "+f"(c[3])
        : "r"(a[0]), "r"(a[1]), "r"(a[2]), "r"(a[3]), "r"(b[0]), "r"(b[1]));
}

// ---------------------------------------------------------------------------
// split_x: x NCHW fp32 -> [b][y][t][256ic] fp16 hi/lo
// ---------------------------------------------------------------------------
__global__ void split_x_k(const float* __restrict__ x,
                          __half* __restrict__ xh,
                          __half* __restrict__ xl) {
    extern __shared__ float s[];               // [256 ic][65]
    const int y = blockIdx.x, b = blockIdx.y, tid = threadIdx.x;
    for (int r = 0; r < 64; r++) {
        int idx = r * 256 + tid, ic = idx >> 6, t = idx & 63;
        s[ic * 65 + t] = x[(((size_t)b * 256 + ic) * 256 + y) * 64 + t];
    }
    __syncthreads();
    size_t ob = ((size_t)(b * 256 + y)) * 64 * 256;
    for (int r = 0; r < 32; r++) {
        int idx = r * 512 + tid * 2, t = idx >> 8, ic = idx & 255;
        float f0 = s[ic * 65 + t], f1 = s[(ic + 1) * 65 + t];
        uint32_t hp, lp;
        split2h(f0, f1, hp, lp);
        *(uint32_t*)(xh + ob + (size_t)t * 256 + ic) = hp;
        *(uint32_t*)(xl + ob + (size_t)t * 256 + ic) = lp;
    }
}

// ---------------------------------------------------------------------------
// Weight packing: w[oc][ic][3][3] fp32 -> [oc][icchunk][tap][16ic] fp16 (hi only)
// ---------------------------------------------------------------------------
__global__ void pack_w1_k(const float* __restrict__ wq,
                          const float* __restrict__ wk,
                          const float* __restrict__ wv) {
    int id = blockIdx.x * blockDim.x + threadIdx.x;
    if (id >= 192 * 2304) return;
    int oc = id / 2304, kp = id % 2304;
    int chunk = kp / 144, rem = kp % 144, tap = rem / 16, i = rem & 15;
    int ic = chunk * 16 + i;
    float v;
    if (oc < 32)       v = wq[(oc * 256 + ic) * 9 + tap];
    else if (oc < 64)  v = wk[((oc - 32) * 256 + ic) * 9 + tap];
    else               v = wv[((oc - 64) * 256 + ic) * 9 + tap];
    g_w1h[id] = __float2half_rn(v);
}

__global__ void pack_w2_k(const float* __restrict__ wo) {
    int id = blockIdx.x * blockDim.x + threadIdx.x;
    if (id >= 256 * 1152) return;
    int oc = id / 1152, kp = id % 1152;
    int chunk = kp / 144, rem = kp % 144, tap = rem / 16, i = rem & 15;
    int ic = chunk * 16 + i;
    g_w2h[id] = __float2half_rn(wo[(oc * 128 + ic) * 9 + tap]);
}

// ---------------------------------------------------------------------------
// conv3x3 via mma.sync fp16 (activation hi/lo split, 2 passes; weights hi only).
// CTA: 256 thr (8 warps: 4 m x 2 n), 2 CTAs/SM. M=256 positions
// (4 V-rows x 64 T) x N=64 oc. Chunk = 16 ic.
// A and B both double-buffered (cp.async), one commit group per chunk.
// Patch: [6 rows][66 cols] pixels of 48B stride (32B payload), hi/lo regions.
// B: [64 oc][304B stride: 9 taps x 16 ic] fp16 hi.
// ---------------------------------------------------------------------------
#define A_LO    19008          // lo offset within one A buffer (6*66*48)
#define A_BUF   38016          // one A buffer (hi+lo)
#define BH_O    76032          // B base (2*A_BUF)
#define B_BUF   19456          // one B buffer (64*304)
#define CONV_SMEM 114944       // BH_O + 2*B_BUF

template<int ICC, int OCTOT, bool TRANS>
__global__ __launch_bounds__(256, 2)
void conv_mma(const __half* __restrict__ inh,
              const __half* __restrict__ inl,
              const __half* __restrict__ wh,
              __nv_bfloat16* __restrict__ outh,
              __nv_bfloat16* __restrict__ outl,
              float* __restrict__ out32,
              const float* __restrict__ resid,
              const float* __restrict__ sigma) {
    constexpr int IC = ICC * 16;
    extern __shared__ char sm[];

    const int tid  = threadIdx.x;
    const int lane = tid & 31;
    const int w    = tid >> 5;
    const int ocB  = blockIdx.x * 64;
    const int y0   = blockIdx.y * 4;
    const int b    = blockIdx.z;
    const int m0   = (w & 3) * 64;
    const int n0   = (w >> 2) * 32;
    const uint32_t su = smem_u32(sm);

    float acc[4][4][4];
#pragma unroll
    for (int i = 0; i < 4; i++)
#pragma unroll
        for (int j = 0; j < 4; j++)
#pragma unroll
            for (int e = 0; e < 4; e++) acc[i][j][e] = 0.f;

    // stage A patch for chunk c into buffer buf: 6x66 pixels, hi+lo (32B each)
    auto stageA = [&](int c, int buf) {
        uint32_t au = su + buf * A_BUF;
        for (int i = tid; i < 792; i += 256) {
            int half = i & 1, p = i >> 1;
            int row = p / 66, col = p - row * 66;
            int gy = y0 + row - 1, gt = col - 1;
            bool ok = ((unsigned)gy < 256u) && ((unsigned)gt < 64u);
            const __half* base = half ? inl : inh;
            const __half* src = ok
                ? base + ((size_t)((b * 256 + gy) * 64 + gt)) * IC + c * 16
                : base;
            uint32_t dst = au + half * A_LO + (uint32_t)(row * 66 + col) * 48;
            int sz = ok ? 16 : 0;
            CP16(dst, src, sz);
            CP16(dst + 16, src + 8, sz);
        }
    };
    // stage B for chunk c into buffer buf: 64 oc x 18 segs of 16B (fp16 hi)
    auto stageB = [&](int c, int buf) {
        for (int i = tid; i < 1152; i += 256) {
            int n = i / 18, seg = i - n * 18;
            const __half* src = wh + ((size_t)(ocB + n) * ICC + c) * 144 + seg * 8;
            uint32_t dst = su + BH_O + buf * B_BUF + n * 304 + seg * 16;
            CP16(dst, src, 16);
        }
    };

    stageA(0, 0);
    stageB(0, 0);
    CP_COMMIT();

    const int l16 = lane & 15;
    // B ldmatrix lane mapping: one LDMX4 covers 2 n-tiles (k0+k8 each)
    const int bg   = lane >> 3;                    // 0..3
    const int brow = (bg >> 1) * 8 + (lane & 7);   // n-row within pair
    const int bko  = (bg & 1) * 16;                // k-offset bytes

    for (int c = 0; c < ICC; ++c) {
        if (c + 1 < ICC) {
            stageA(c + 1, (c + 1) & 1);
            stageB(c + 1, (c + 1) & 1);
            CP_COMMIT();
            CP_WAIT(1);        // chunk c complete; c+1 in flight
        } else {
            CP_WAIT(0);
        }
        __syncthreads();

        const uint32_t sa = su + (c & 1) * A_BUF;
        const uint32_t sb = su + BH_O + (c & 1) * B_BUF;
#pragma unroll
        for (int tap = 0; tap < 9; ++tap) {
            const int ky = tap / 3, kx = tap - ky * 3;
            // B fragments: 2 LDMX4 for 4 n-tiles (fp16 hi)
            uint32_t bf0[4], bf1[4];
            {
                uint32_t ad = sb + (n0 + brow) * 304 + tap * 32 + bko;
                LDMX4(bf0, ad);
                LDMX4(bf1, ad + 16 * 304);
            }
#pragma unroll
            for (int mp = 0; mp < 2; ++mp) {
                uint32_t a0h[4], a0l[4], a1h[4], a1l[4];
                {
                    int mrow = m0 + (2 * mp) * 16 + l16;
                    int rp = (mrow >> 6) + ky, cp = (mrow & 63) + kx;
                    uint32_t ad = sa + (uint32_t)(rp * 66 + cp) * 48 + (lane >> 4) * 16;
                    LDMX4(a0h, ad);
                    LDMX4(a0l, ad + A_LO);
                }
                {
                    int mrow = m0 + (2 * mp + 1) * 16 + l16;
                    int rp = (mrow >> 6) + ky, cp = (mrow & 63) + kx;
                    uint32_t ad = sa + (uint32_t)(rp * 66 + cp) * 48 + (lane >> 4) * 16;
                    LDMX4(a1h, ad);
                    LDMX4(a1l, ad + A_LO);
                }
                // pass-major: hi pass then lo pass (dep distance 8)
                mma16816h(acc[2 * mp][0],     a0h, &bf0[0]);
                mma16816h(acc[2 * mp][1],     a0h, &bf0[2]);
                mma16816h(acc[2 * mp][2],     a0h, &bf1[0]);
                mma16816h(acc[2 * mp][3],     a0h, &bf1[2]);
                mma16816h(acc[2 * mp + 1][0], a1h, &bf0[0]);
                mma16816h(acc[2 * mp + 1][1], a1h, &bf0[2]);
                mma16816h(acc[2 * mp + 1][2], a1h, &bf1[0]);
                mma16816h(acc[2 * mp + 1][3], a1h, &bf1[2]);
                mma16816h(acc[2 * mp][0],     a0l, &bf0[0]);
                mma16816h(acc[2 * mp][1],     a0l, &bf0[2]);
                mma16816h(acc[2 * mp][2],     a0l, &bf1[0]);
                mma16816h(acc[2 * mp][3],     a0l, &bf1[2]);
                mma16816h(acc[2 * mp + 1][0], a1l, &bf0[0]);
                mma16816h(acc[2 * mp + 1][1], a1l, &bf0[2]);
                mma16816h(acc[2 * mp + 1][2], a1l, &bf1[0]);
                mma16816h(acc[2 * mp + 1][3], a1l, &bf1[2]);
            }
        }
        __syncthreads();       // protect buffer reuse
    }

    // ---- epilogue ----
    const int r0l = lane >> 2, c0l = (lane & 3) * 2;
    if constexpr (TRANS) {
#pragma unroll
        for (int mt = 0; mt < 4; ++mt)
#pragma unroll
            for (int nt = 0; nt < 4; ++nt) {
                int oc = ocB + n0 + nt * 8 + c0l;
#pragma unroll
                for (int h = 0; h < 2; ++h) {
                    int m = m0 + mt * 16 + r0l + h * 8;
                    int v = y0 + (m >> 6), t = m & 63;
                    uint32_t hp, lp;
                    split2(acc[mt][nt][h * 2], acc[mt][nt][h * 2 + 1], hp, lp);
                    size_t base = ((size_t)((b * 64 + t) * 256 + v)) * OCTOT + oc;
                    *(uint32_t*)(outh + base) = hp;
                    *(uint32_t*)(outl + base) = lp;
                }
            }
    } else {
        float sg = sigma[0];
#pragma unroll
        for (int mt = 0; mt < 4; ++mt)
#pragma unroll
            for (int nt = 0; nt < 4; ++nt)
#pragma unroll
                for (int h = 0; h < 2; ++h) {
                    int m = m0 + mt * 16 + r0l + h * 8;
                    int v = y0 + (m >> 6), t = m & 63;
#pragma unroll
                    for (int e = 0; e < 2; ++e) {
                        int oc = ocB + n0 + nt * 8 + c0l + e;
                        size_t idx = (((size_t)b * OCTOT + oc) * 256 + v) * 64 + t;
                        out32[idx] = resid[idx] + sg * acc[mt][nt][h * 2 + e];
                    }
                }
    }
}

// ---------------------------------------------------------------------------
// Attention via mma.sync bf16 hi/lo (flash-style online softmax), unchanged
// except the output is written as fp16 hi/lo for conv2.
// One CTA per (b,t): 512 thr, 16 warps, warp owns 16 query rows.
// ---------------------------------------------------------------------------
#define QH_O 0
#define QL_O 20480
#define KH_O 40960
#define KL_O 61440
#define VH_O 81920
#define VL_O 151552
#define ATTN_SMEM 221184

__global__ __launch_bounds__(512, 1)
void attn_kernel(const __nv_bfloat16* __restrict__ qh,
                 const __nv_bfloat16* __restrict__ ql,
                 __half* __restrict__ avh,
                 __half* __restrict__ avl) {
    extern __shared__ char smc[];
    const int tid  = threadIdx.x;
    const int lane = tid & 31;
    const int w    = tid >> 5;
    const int t    = blockIdx.x;
    const int b    = blockIdx.y;
    const uint32_t su = smem_u32(smc);

    const size_t sbase = ((size_t)(b * 64 + t)) * 256 * 192;
    for (int idx = tid; idx < 12288; idx += 512) {
        int half = idx >= 6144;
        int r = half ? idx - 6144 : idx;
        int row = r / 24, seg = r - row * 24;
        float4 val = *(const float4*)((half ? ql : qh) + sbase + (size_t)row * 192 + seg * 8);
        uint32_t dst;
        if (seg < 4)       dst = (half ? QL_O : QH_O) + row * 80 + seg * 16;
        else if (seg < 8)  dst = (half ? KL_O : KH_O) + row * 80 + (seg - 4) * 16;
        else               dst = (half ? VL_O : VH_O) + row * 272 + (seg - 8) * 16;
        *(float4*)(smc + dst) = val;
    }
    __syncthreads();

    const int q0  = w * 16;
    const int l16 = lane & 15;

    float o[16][4];
#pragma unroll
    for (int i = 0; i < 16; i++)
#pragma unroll
        for (int j = 0; j < 4; j++) o[i][j] = 0.f;
    float mrow[2] = {-1e30f, -1e30f};
    float lrow[2] = {0.f, 0.f};

    for (int c0 = 0; c0 < 4; ++c0) {
        float s[8][4];
#pragma unroll
        for (int i = 0; i < 8; i++)
#pragma unroll
            for (int j = 0; j < 4; j++) s[i][j] = 0.f;

#pragma unroll
        for (int kk = 0; kk < 2; ++kk) {
            uint32_t aH[4], aL[4];
            uint32_t qa = su + QH_O + (q0 + l16) * 80 + (lane >> 4) * 16 + kk * 32;
            LDMX4(aH, qa);
            LDMX4(aL, qa + (QL_O - QH_O));
#pragma unroll
            for (int np = 0; np < 2; ++np) {
                uint32_t kh0[4], kl0[4], kh1[4], kl1[4];
                uint32_t ka0 = su + KH_O + (c0 * 64 + (2 * np) * 16 + l16) * 80
                             + (lane >> 4) * 16 + kk * 32;
                LDMX4(kh0, ka0);
                LDMX4(kl0, ka0 + (KL_O - KH_O));
                LDMX4(kh1, ka0 + 16 * 80);
                LDMX4(kl1, ka0 + 16 * 80 + (KL_O - KH_O));
                uint32_t b0h[2] = {kh0[0], kh0[2]}, b1h[2] = {kh0[1], kh0[3]};
                uint32_t b2h[2] = {kh1[0], kh1[2]}, b3h[2] = {kh1[1], kh1[3]};
                uint32_t b0l[2] = {kl0[0], kl0[2]}, b1l[2] = {kl0[1], kl0[3]};
                uint32_t b2l[2] = {kl1[0], kl1[2]}, b3l[2] = {kl1[1], kl1[3]};
                float* s0 = s[4 * np]; float* s1 = s[4 * np + 1];
                float* s2 = s[4 * np + 2]; float* s3 = s[4 * np + 3];
                mma16816(s0, aH, b0h); mma16816(s1, aH, b1h);
                mma16816(s2, aH, b2h); mma16816(s3, aH, b3h);
                mma16816(s0, aL, b0h); mma16816(s1, aL, b1h);
                mma16816(s2, aL, b2h); mma16816(s3, aL, b3h);
                mma16816(s0, aH, b0l); mma16816(s1, aH, b1l);
                mma16816(s2, aH, b2l); mma16816(s3, aH, b3l);
            }
        }

#pragma unroll
        for (int h = 0; h < 2; ++h) {
            float mc = -1e30f;
#pragma unroll
            for (int nt = 0; nt < 8; ++nt)
                mc = fmaxf(mc, fmaxf(s[nt][2 * h], s[nt][2 * h + 1]));
            mc = fmaxf(mc, __shfl_xor_sync(0xffffffffu, mc, 1));
            mc = fmaxf(mc, __shfl_xor_sync(0xffffffffu, mc, 2));
            float mn = fmaxf(mrow[h], mc);
            float sc = __expf(mrow[h] - mn);
            mrow[h] = mn;
            float ls = 0.f;
#pragma unroll
            for (int nt = 0; nt < 8; ++nt) {
                float p0 = __expf(s[nt][2 * h] - mn);
                float p1 = __expf(s[nt][2 * h + 1] - mn);
                s[nt][2 * h] = p0; s[nt][2 * h + 1] = p1;
                ls += p0 + p1;
            }
            ls += __shfl_xor_sync(0xffffffffu, ls, 1);
            ls += __shfl_xor_sync(0xffffffffu, ls, 2);
            lrow[h] = lrow[h] * sc + ls;
#pragma unroll
            for (int nt = 0; nt < 16; ++nt) {
                o[nt][2 * h]     *= sc;
                o[nt][2 * h + 1] *= sc;
            }
        }

#pragma unroll
        for (int kk = 0; kk < 4; ++kk) {
            uint32_t ph[4], pl[4];
            split2(s[2 * kk][0],     s[2 * kk][1],     ph[0], pl[0]);
            split2(s[2 * kk][2],     s[2 * kk][3],     ph[1], pl[1]);
            split2(s[2 * kk + 1][0], s[2 * kk + 1][1], ph[2], pl[2]);
            split2(s[2 * kk + 1][2], s[2 * kk + 1][3], ph[3], pl[3]);
#pragma unroll
            for (int np = 0; np < 4; ++np) {
                uint32_t vh0[4], vl0[4], vh1[4], vl1[4];
                uint32_t va = su + VH_O + (c0 * 64 + kk * 16 + l16) * 272
                            + (lane >> 4) * 16 + (2 * np) * 32;
                LDMX4T(vh0, va);
                LDMX4T(vl0, va + (VL_O - VH_O));
                LDMX4T(vh1, va + 32);
                LDMX4T(vl1, va + 32 + (VL_O - VH_O));
                uint32_t bh0[2] = {vh0[0], vh0[1]}, bh1[2] = {vh0[2], vh0[3]};
                uint32_t bh2[2] = {vh1[0], vh1[1]}, bh3[2] = {vh1[2], vh1[3]};
                uint32_t bl0[2] = {vl0[0], vl0[1]}, bl1[2] = {vl0[2], vl0[3]};
                uint32_t bl2[2] = {vl1[0], vl1[1]}, bl3[2] = {vl1[2], vl1[3]};
                float* o0 = o[4 * np]; float* o1 = o[4 * np + 1];
                float* o2 = o[4 * np + 2]; float* o3 = o[4 * np + 3];
                mma16816(o0, ph, bh0); mma16816(o1, ph, bh1);
                mma16816(o2, ph, bh2); mma16816(o3, ph, bh3);
                mma16816(o0, pl, bh0); mma16816(o1, pl, bh1);
                mma16816(o2, pl, bh2); mma16816(o3, pl, bh3);
                mma16816(o0, ph, bl0); mma16816(o1, ph, bl1);
                mma16816(o2, ph, bl2); mma16816(o3, ph, bl3);
            }
        }
    }

    // ---- epilogue: normalize, split fp16, store [b][v][t][128] ----
    float rin[2] = {1.f / lrow[0], 1.f / lrow[1]};
#pragma unroll
    for (int nt = 0; nt < 16; ++nt) {
        int ch = nt * 8 + (lane & 3) * 2;
#pragma unroll
        for (int h = 0; h < 2; ++h) {
            int v = q0 + (lane >> 2) + h * 8;
            float f0 = o[nt][2 * h] * rin[h];
            float f1 = o[nt][2 * h + 1] * rin[h];
            uint32_t hp, lp;
            split2h(f0, f1, hp, lp);
            size_t ad = ((size_t)(b * 256 + v) * 64 + t) * 128 + ch;
            *(uint32_t*)(avh + ad) = hp;
            *(uint32_t*)(avl + ad) = lp;
        }
    }
}

// ---------------------------------------------------------------------------
extern "C" void kernel_launch(void* const* d_in, const int* in_sizes, int n_in,
                              void* d_out, int out_size) {
    const float* x     = (const float*)d_in[0];
    const float* wq    = (const float*)d_in[1];
    const float* wk    = (const float*)d_in[2];
    const float* wv    = (const float*)d_in[3];
    const float* wo    = (const float*)d_in[4];
    const float* sigma = (const float*)d_in[5];
    float* out = (float*)d_out;

    __half *xh, *xl, *avh, *avl, *w1h, *w2h;
    __nv_bfloat16 *qkvh, *qkvl;
    cudaGetSymbolAddress((void**)&xh,   g_xh);
    cudaGetSymbolAddress((void**)&xl,   g_xl);
    cudaGetSymbolAddress((void**)&qkvh, g_qkvh);
    cudaGetSymbolAddress((void**)&qkvl, g_qkvl);
    cudaGetSymbolAddress((void**)&avh,  g_avh);
    cudaGetSymbolAddress((void**)&avl,  g_avl);
    cudaGetSymbolAddress((void**)&w1h,  g_w1h);
    cudaGetSymbolAddress((void**)&w2h,  g_w2h);

    cudaFuncSetAttribute(split_x_k,
                         cudaFuncAttributeMaxDynamicSharedMemorySize, 66560);
    split_x_k<<<dim3(256, 8), 256, 66560>>>(x, xh, xl);

    pack_w1_k<<<(192 * 2304 + 255) / 256, 256>>>(wq, wk, wv);
    pack_w2_k<<<(256 * 1152 + 255) / 256, 256>>>(wo);

    {   // conv1: IC=256 (16 chunks), OCTOT=192, split-bf16 transposed output
        auto k = conv_mma<16, 192, true>;
        cudaFuncSetAttribute(k, cudaFuncAttributeMaxDynamicSharedMemorySize,
                             CONV_SMEM);
        k<<<dim3(3, 64, 8), 256, CONV_SMEM>>>(xh, xl, w1h,
                                              qkvh, qkvl, nullptr, nullptr, nullptr);
    }

    cudaFuncSetAttribute(attn_kernel,
                         cudaFuncAttributeMaxDynamicSharedMemorySize, ATTN_SMEM);
    attn_kernel<<<dim3(T_, B_), 512, ATTN_SMEM>>>(qkvh, qkvl, avh, avl);

    {   // conv2: IC=128 (8 chunks), OCTOT=256, fp32 out + residual
        auto k = conv_mma<8, 256, false>;
        cudaFuncSetAttribute(k, cudaFuncAttributeMaxDynamicSharedMemorySize,
                             CONV_SMEM);
        k<<<dim3(4, 64, 8), 256, CONV_SMEM>>>(avh, avl, w2h,
                                              nullptr, nullptr, out, x, sigma);
    }
}

// round 10
// speedup vs baseline: 1.7199x; 1.1931x over previous
#include <cuda_runtime.h>
#include <cuda_bf16.h>
#include <cuda_fp16.h>
#include <cstdint>

#define B_   8
#define V_   256
#define T_   64

// ---------------------------------------------------------------------------
// Global scratch
// ---------------------------------------------------------------------------
__device__ __half g_xh[8ll * 256 * 64 * 256];            // [b][v][t][256ic] fp16
__device__ __half g_xl[8ll * 256 * 64 * 256];
__device__ __nv_bfloat16 g_qkvh[8ll * 64 * 256 * 192];   // [b][t][v][192] bf16
__device__ __nv_bfloat16 g_qkvl[8ll * 64 * 256 * 192];
__device__ __half g_avh[8ll * 256 * 64 * 128];           // [b][v][t][128ic] fp16
__device__ __half g_w1h[192 * 2304];                     // [oc][chunk][tap][16] fp16
__device__ __half g_w2h[256 * 1152];

// ---------------------------------------------------------------------------
// Helpers
// ---------------------------------------------------------------------------
__device__ __forceinline__ uint32_t smem_u32(const void* p) {
    return (uint32_t)__cvta_generic_to_shared(p);
}
__device__ __forceinline__ uint32_t pack2bf(float f0, float f1) {
    __nv_bfloat162 h = __floats2bfloat162_rn(f0, f1);
    return *(uint32_t*)&h;
}
__device__ __forceinline__ void split2(float f0, float f1,
                                       uint32_t& hp, uint32_t& lp) {
    hp = pack2bf(f0, f1);
    float h0 = __uint_as_float(hp << 16);
    float h1 = __uint_as_float(hp & 0xFFFF0000u);
    lp = pack2bf(f0 - h0, f1 - h1);
}
__device__ __forceinline__ void split2h(float f0, float f1,
                                        uint32_t& hp, uint32_t& lp) {
    __half2 h = __floats2half2_rn(f0, f1);
    hp = *(uint32_t*)&h;
    float r0 = f0 - __half2float(__low2half(h));
    float r1 = f1 - __half2float(__high2half(h));
    __half2 l = __floats2half2_rn(r0, r1);
    lp = *(uint32_t*)&l;
}

#define LDMX4(r, a) \
    asm volatile("ldmatrix.sync.aligned.m8n8.x4.shared.b16 {%0,%1,%2,%3},[%4];" \
        : "=r"((r)[0]), "=r"((r)[1]), "=r"((r)[2]), "=r"((r)[3]) : "r"(a))
#define LDMX4T(r, a) \
    asm volatile("ldmatrix.sync.aligned.m8n8.x4.trans.shared.b16 {%0,%1,%2,%3},[%4];" \
        : "=r"((r)[0]), "=r"((r)[1]), "=r"((r)[2]), "=r"((r)[3]) : "r"(a))
#define CP16(dst, src, sz) \
    asm volatile("cp.async.cg.shared.global [%0], [%1], 16, %2;" \
                 :: "r"(dst), "l"(src), "r"(sz) : "memory")
#define CP_COMMIT() asm volatile("cp.async.commit_group;" ::: "memory")
#define CP_WAIT(n)  asm volatile("cp.async.wait_group %0;" :: "n"(n) : "memory")

__device__ __forceinline__ void mma16816(float* c, const uint32_t* a, const uint32_t* b) {
    asm volatile(
        "mma.sync.aligned.m16n8k16.row.col.f32.bf16.bf16.f32 "
        "{%0,%1,%2,%3},{%4,%5,%6,%7},{%8,%9},{%0,%1,%2,%3};"
        : "+f"(c[0]), "+f"(c[1]), "+f"(c[2]), "+f"(c[3])
        : "r"(a[0]), "r"(a[1]), "r"(a[2]), "r"(a[3]), "r"(b[0]), "r"(b[1]));
}
__device__ __forceinline__ void mma16816h(float* c, const uint32_t* a, const uint32_t* b) {
    asm volatile(
        "mma.sync.aligned.m16n8k16.row.col.f32.f16.f16.f32 "
        "{%0,%1,%2,%3},{%4,%5,%6,%7},{%8,%9},{%0,%1,%2,%3};"
        : "+f"(c[0]), "+f"(c[1]), "+f"(c[2]), "+f"(c[3])
        : "r"(a[0]), "r"(a[1]), "r"(a[2]), "r"(a[3]), "r"(b[0]), "r"(b[1]));
}

// ---------------------------------------------------------------------------
// split_x: x NCHW fp32 -> [b][y][t][256ic] fp16 hi/lo
// ---------------------------------------------------------------------------
__global__ void split_x_k(const float* __restrict__ x,
                          __half* __restrict__ xh,
                          __half* __restrict__ xl) {
    extern __shared__ float s[];               // [256 ic][65]
    const int y = blockIdx.x, b = blockIdx.y, tid = threadIdx.x;
    for (int r = 0; r < 64; r++) {
        int idx = r * 256 + tid, ic = idx >> 6, t = idx & 63;
        s[ic * 65 + t] = x[(((size_t)b * 256 + ic) * 256 + y) * 64 + t];
    }
    __syncthreads();
    size_t ob = ((size_t)(b * 256 + y)) * 64 * 256;
    for (int r = 0; r < 32; r++) {
        int idx = r * 512 + tid * 2, t = idx >> 8, ic = idx & 255;
        float f0 = s[ic * 65 + t], f1 = s[(ic + 1) * 65 + t];
        uint32_t hp, lp;
        split2h(f0, f1, hp, lp);
        *(uint32_t*)(xh + ob + (size_t)t * 256 + ic) = hp;
        *(uint32_t*)(xl + ob + (size_t)t * 256 + ic) = lp;
    }
}

// ---------------------------------------------------------------------------
// Weight packing: w[oc][ic][3][3] fp32 -> [oc][icchunk][tap][16ic] fp16
// ---------------------------------------------------------------------------
__global__ void pack_w1_k(const float* __restrict__ wq,
                          const float* __restrict__ wk,
                          const float* __restrict__ wv) {
    int id = blockIdx.x * blockDim.x + threadIdx.x;
    if (id >= 192 * 2304) return;
    int oc = id / 2304, kp = id % 2304;
    int chunk = kp / 144, rem = kp % 144, tap = rem / 16, i = rem & 15;
    int ic = chunk * 16 + i;
    float v;
    if (oc < 32)       v = wq[(oc * 256 + ic) * 9 + tap];
    else if (oc < 64)  v = wk[((oc - 32) * 256 + ic) * 9 + tap];
    else               v = wv[((oc - 64) * 256 + ic) * 9 + tap];
    g_w1h[id] = __float2half_rn(v);
}

__global__ void pack_w2_k(const float* __restrict__ wo) {
    int id = blockIdx.x * blockDim.x + threadIdx.x;
    if (id >= 256 * 1152) return;
    int oc = id / 1152, kp = id % 1152;
    int chunk = kp / 144, rem = kp % 144, tap = rem / 16, i = rem & 15;
    int ic = chunk * 16 + i;
    g_w2h[id] = __float2half_rn(wo[(oc * 128 + ic) * 9 + tap]);
}

// ---------------------------------------------------------------------------
// conv3x3 via mma.sync fp16.  TWOPASS: activation hi/lo split (2 passes);
// else single-pass (activation hi only).  Weights fp16 single.
// CTA: 256 thr (8 warps: 4 m x 2 n), 2 CTAs/SM. M=256 positions x N=64 oc.
// Chunk = 16 ic.  A and B double-buffered (cp.async).
// Patch: [6 rows][66 cols] pixels of 48B stride. B: [64 oc][304B stride].
// ---------------------------------------------------------------------------
#define B_BUF   19456          // one B buffer (64*304)

template<int ICC, int OCTOT, bool TRANS, bool TWOPASS>
__global__ __launch_bounds__(256, 2)
void conv_mma(const __half* __restrict__ inh,
              const __half* __restrict__ inl,
              const __half* __restrict__ wh,
              __nv_bfloat16* __restrict__ outh,
              __nv_bfloat16* __restrict__ outl,
              float* __restrict__ out32,
              const float* __restrict__ resid,
              const float* __restrict__ sigma) {
    constexpr int IC   = ICC * 16;
    constexpr int A_LO = 19008;                       // lo region offset (if TWOPASS)
    constexpr int ABUF = TWOPASS ? 38016 : 19008;     // one A buffer
    constexpr int BH_O = 2 * ABUF;                    // B base
    extern __shared__ char sm[];

    const int tid  = threadIdx.x;
    const int lane = tid & 31;
    const int w    = tid >> 5;
    const int ocB  = blockIdx.x * 64;
    const int y0   = blockIdx.y * 4;
    const int b    = blockIdx.z;
    const int m0   = (w & 3) * 64;
    const int n0   = (w >> 2) * 32;
    const uint32_t su = smem_u32(sm);

    float acc[4][4][4];
#pragma unroll
    for (int i = 0; i < 4; i++)
#pragma unroll
        for (int j = 0; j < 4; j++)
#pragma unroll
            for (int e = 0; e < 4; e++) acc[i][j][e] = 0.f;

    auto stageA = [&](int c, int buf) {
        uint32_t au = su + buf * ABUF;
        constexpr int NIT = TWOPASS ? 792 : 396;
        for (int i = tid; i < NIT; i += 256) {
            int half, p;
            if constexpr (TWOPASS) { half = i & 1; p = i >> 1; }
            else                   { half = 0;     p = i; }
            int row = p / 66, col = p - row * 66;
            int gy = y0 + row - 1, gt = col - 1;
            bool ok = ((unsigned)gy < 256u) && ((unsigned)gt < 64u);
            const __half* base = half ? inl : inh;
            const __half* src = ok
                ? base + ((size_t)((b * 256 + gy) * 64 + gt)) * IC + c * 16
                : base;
            uint32_t dst = au + half * A_LO + (uint32_t)(row * 66 + col) * 48;
            int sz = ok ? 16 : 0;
            CP16(dst, src, sz);
            CP16(dst + 16, src + 8, sz);
        }
    };
    auto stageB = [&](int c, int buf) {
        for (int i = tid; i < 1152; i += 256) {
            int n = i / 18, seg = i - n * 18;
            const __half* src = wh + ((size_t)(ocB + n) * ICC + c) * 144 + seg * 8;
            uint32_t dst = su + BH_O + buf * B_BUF + n * 304 + seg * 16;
            CP16(dst, src, 16);
        }
    };

    stageA(0, 0);
    stageB(0, 0);
    CP_COMMIT();

    const int l16 = lane & 15;
    const int bg   = lane >> 3;
    const int brow = (bg >> 1) * 8 + (lane & 7);
    const int bko  = (bg & 1) * 16;

    for (int c = 0; c < ICC; ++c) {
        if (c + 1 < ICC) {
            stageA(c + 1, (c + 1) & 1);
            stageB(c + 1, (c + 1) & 1);
            CP_COMMIT();
            CP_WAIT(1);
        } else {
            CP_WAIT(0);
        }
        __syncthreads();

        const uint32_t sa = su + (c & 1) * ABUF;
        const uint32_t sb = su + BH_O + (c & 1) * B_BUF;
#pragma unroll
        for (int tap = 0; tap < 9; ++tap) {
            const int ky = tap / 3, kx = tap - ky * 3;
            uint32_t bf0[4], bf1[4];
            {
                uint32_t ad = sb + (n0 + brow) * 304 + tap * 32 + bko;
                LDMX4(bf0, ad);
                LDMX4(bf1, ad + 16 * 304);
            }
#pragma unroll
            for (int mp = 0; mp < 2; ++mp) {
                uint32_t a0h[4], a1h[4];
                uint32_t a0l[4], a1l[4];
                {
                    int mrow = m0 + (2 * mp) * 16 + l16;
                    int rp = (mrow >> 6) + ky, cp = (mrow & 63) + kx;
                    uint32_t ad = sa + (uint32_t)(rp * 66 + cp) * 48 + (lane >> 4) * 16;
                    LDMX4(a0h, ad);
                    if constexpr (TWOPASS) LDMX4(a0l, ad + A_LO);
                }
                {
                    int mrow = m0 + (2 * mp + 1) * 16 + l16;
                    int rp = (mrow >> 6) + ky, cp = (mrow & 63) + kx;
                    uint32_t ad = sa + (uint32_t)(rp * 66 + cp) * 48 + (lane >> 4) * 16;
                    LDMX4(a1h, ad);
                    if constexpr (TWOPASS) LDMX4(a1l, ad + A_LO);
                }
                mma16816h(acc[2 * mp][0],     a0h, &bf0[0]);
                mma16816h(acc[2 * mp][1],     a0h, &bf0[2]);
                mma16816h(acc[2 * mp][2],     a0h, &bf1[0]);
                mma16816h(acc[2 * mp][3],     a0h, &bf1[2]);
                mma16816h(acc[2 * mp + 1][0], a1h, &bf0[0]);
                mma16816h(acc[2 * mp + 1][1], a1h, &bf0[2]);
                mma16816h(acc[2 * mp + 1][2], a1h, &bf1[0]);
                mma16816h(acc[2 * mp + 1][3], a1h, &bf1[2]);
                if constexpr (TWOPASS) {
                    mma16816h(acc[2 * mp][0],     a0l, &bf0[0]);
                    mma16816h(acc[2 * mp][1],     a0l, &bf0[2]);
                    mma16816h(acc[2 * mp][2],     a0l, &bf1[0]);
                    mma16816h(acc[2 * mp][3],     a0l, &bf1[2]);
                    mma16816h(acc[2 * mp + 1][0], a1l, &bf0[0]);
                    mma16816h(acc[2 * mp + 1][1], a1l, &bf0[2]);
                    mma16816h(acc[2 * mp + 1][2], a1l, &bf1[0]);
                    mma16816h(acc[2 * mp + 1][3], a1l, &bf1[2]);
                }
            }
        }
        __syncthreads();
    }

    // ---- epilogue ----
    const int r0l = lane >> 2, c0l = (lane & 3) * 2;
    if constexpr (TRANS) {
#pragma unroll
        for (int mt = 0; mt < 4; ++mt)
#pragma unroll
            for (int nt = 0; nt < 4; ++nt) {
                int oc = ocB + n0 + nt * 8 + c0l;
#pragma unroll
                for (int h = 0; h < 2; ++h) {
                    int m = m0 + mt * 16 + r0l + h * 8;
                    int v = y0 + (m >> 6), t = m & 63;
                    uint32_t hp, lp;
                    split2(acc[mt][nt][h * 2], acc[mt][nt][h * 2 + 1], hp, lp);
                    size_t base = ((size_t)((b * 64 + t) * 256 + v)) * OCTOT + oc;
                    *(uint32_t*)(outh + base) = hp;
                    *(uint32_t*)(outl + base) = lp;
                }
            }
    } else {
        float sg = sigma[0];
#pragma unroll
        for (int mt = 0; mt < 4; ++mt)
#pragma unroll
            for (int nt = 0; nt < 4; ++nt)
#pragma unroll
                for (int h = 0; h < 2; ++h) {
                    int m = m0 + mt * 16 + r0l + h * 8;
                    int v = y0 + (m >> 6), t = m & 63;
#pragma unroll
                    for (int e = 0; e < 2; ++e) {
                        int oc = ocB + n0 + nt * 8 + c0l + e;
                        size_t idx = (((size_t)b * OCTOT + oc) * 256 + v) * 64 + t;
                        out32[idx] = resid[idx] + sg * acc[mt][nt][h * 2 + e];
                    }
                }
    }
}

// ---------------------------------------------------------------------------
// Attention via mma.sync bf16 hi/lo (flash-style online softmax).
// Output: single fp16 [b][v][t][128] (conv2 is single-pass).
// ---------------------------------------------------------------------------
#define QH_O 0
#define QL_O 20480
#define KH_O 40960
#define KL_O 61440
#define VH_O 81920
#define VL_O 151552
#define ATTN_SMEM 221184

__global__ __launch_bounds__(512, 1)
void attn_kernel(const __nv_bfloat16* __restrict__ qh,
                 const __nv_bfloat16* __restrict__ ql,
                 __half* __restrict__ avh) {
    extern __shared__ char smc[];
    const int tid  = threadIdx.x;
    const int lane = tid & 31;
    const int w    = tid >> 5;
    const int t    = blockIdx.x;
    const int b    = blockIdx.y;
    const uint32_t su = smem_u32(smc);

    const size_t sbase = ((size_t)(b * 64 + t)) * 256 * 192;
    for (int idx = tid; idx < 12288; idx += 512) {
        int half = idx >= 6144;
        int r = half ? idx - 6144 : idx;
        int row = r / 24, seg = r - row * 24;
        float4 val = *(const float4*)((half ? ql : qh) + sbase + (size_t)row * 192 + seg * 8);
        uint32_t dst;
        if (seg < 4)       dst = (half ? QL_O : QH_O) + row * 80 + seg * 16;
        else if (seg < 8)  dst = (half ? KL_O : KH_O) + row * 80 + (seg - 4) * 16;
        else               dst = (half ? VL_O : VH_O) + row * 272 + (seg - 8) * 16;
        *(float4*)(smc + dst) = val;
    }
    __syncthreads();

    const int q0  = w * 16;
    const int l16 = lane & 15;

    float o[16][4];
#pragma unroll
    for (int i = 0; i < 16; i++)
#pragma unroll
        for (int j = 0; j < 4; j++) o[i][j] = 0.f;
    float mrow[2] = {-1e30f, -1e30f};
    float lrow[2] = {0.f, 0.f};

    for (int c0 = 0; c0 < 4; ++c0) {
        float s[8][4];
#pragma unroll
        for (int i = 0; i < 8; i++)
#pragma unroll
            for (int j = 0; j < 4; j++) s[i][j] = 0.f;

#pragma unroll
        for (int kk = 0; kk < 2; ++kk) {
            uint32_t aH[4], aL[4];
            uint32_t qa = su + QH_O + (q0 + l16) * 80 + (lane >> 4) * 16 + kk * 32;
            LDMX4(aH, qa);
            LDMX4(aL, qa + (QL_O - QH_O));
#pragma unroll
            for (int np = 0; np < 2; ++np) {
                uint32_t kh0[4], kl0[4], kh1[4], kl1[4];
                uint32_t ka0 = su + KH_O + (c0 * 64 + (2 * np) * 16 + l16) * 80
                             + (lane >> 4) * 16 + kk * 32;
                LDMX4(kh0, ka0);
                LDMX4(kl0, ka0 + (KL_O - KH_O));
                LDMX4(kh1, ka0 + 16 * 80);
                LDMX4(kl1, ka0 + 16 * 80 + (KL_O - KH_O));
                uint32_t b0h[2] = {kh0[0], kh0[2]}, b1h[2] = {kh0[1], kh0[3]};
                uint32_t b2h[2] = {kh1[0], kh1[2]}, b3h[2] = {kh1[1], kh1[3]};
                uint32_t b0l[2] = {kl0[0], kl0[2]}, b1l[2] = {kl0[1], kl0[3]};
                uint32_t b2l[2] = {kl1[0], kl1[2]}, b3l[2] = {kl1[1], kl1[3]};
                float* s0 = s[4 * np]; float* s1 = s[4 * np + 1];
                float* s2 = s[4 * np + 2]; float* s3 = s[4 * np + 3];
                mma16816(s0, aH, b0h); mma16816(s1, aH, b1h);
                mma16816(s2, aH, b2h); mma16816(s3, aH, b3h);
                mma16816(s0, aL, b0h); mma16816(s1, aL, b1h);
                mma16816(s2, aL, b2h); mma16816(s3, aL, b3h);
                mma16816(s0, aH, b0l); mma16816(s1, aH, b1l);
                mma16816(s2, aH, b2l); mma16816(s3, aH, b3l);
            }
        }

#pragma unroll
        for (int h = 0; h < 2; ++h) {
            float mc = -1e30f;
#pragma unroll
            for (int nt = 0; nt < 8; ++nt)
                mc = fmaxf(mc, fmaxf(s[nt][2 * h], s[nt][2 * h + 1]));
            mc = fmaxf(mc, __shfl_xor_sync(0xffffffffu, mc, 1));
            mc = fmaxf(mc, __shfl_xor_sync(0xffffffffu, mc, 2));
            float mn = fmaxf(mrow[h], mc);
            float sc = __expf(mrow[h] - mn);
            mrow[h] = mn;
            float ls = 0.f;
#pragma unroll
            for (int nt = 0; nt < 8; ++nt) {
                float p0 = __expf(s[nt][2 * h] - mn);
                float p1 = __expf(s[nt][2 * h + 1] - mn);
                s[nt][2 * h] = p0; s[nt][2 * h + 1] = p1;
                ls += p0 + p1;
            }
            ls += __shfl_xor_sync(0xffffffffu, ls, 1);
            ls += __shfl_xor_sync(0xffffffffu, ls, 2);
            lrow[h] = lrow[h] * sc + ls;
#pragma unroll
            for (int nt = 0; nt < 16; ++nt) {
                o[nt][2 * h]     *= sc;
                o[nt][2 * h + 1] *= sc;
            }
        }

#pragma unroll
        for (int kk = 0; kk < 4; ++kk) {
            uint32_t ph[4], pl[4];
            split2(s[2 * kk][0],     s[2 * kk][1],     ph[0], pl[0]);
            split2(s[2 * kk][2],     s[2 * kk][3],     ph[1], pl[1]);
            split2(s[2 * kk + 1][0], s[2 * kk + 1][1], ph[2], pl[2]);
            split2(s[2 * kk + 1][2], s[2 * kk + 1][3], ph[3], pl[3]);
#pragma unroll
            for (int np = 0; np < 4; ++np) {
                uint32_t vh0[4], vl0[4], vh1[4], vl1[4];
                uint32_t va = su + VH_O + (c0 * 64 + kk * 16 + l16) * 272
                            + (lane >> 4) * 16 + (2 * np) * 32;
                LDMX4T(vh0, va);
                LDMX4T(vl0, va + (VL_O - VH_O));
                LDMX4T(vh1, va + 32);
                LDMX4T(vl1, va + 32 + (VL_O - VH_O));
                uint32_t bh0[2] = {vh0[0], vh0[1]}, bh1[2] = {vh0[2], vh0[3]};
                uint32_t bh2[2] = {vh1[0], vh1[1]}, bh3[2] = {vh1[2], vh1[3]};
                uint32_t bl0[2] = {vl0[0], vl0[1]}, bl1[2] = {vl0[2], vl0[3]};
                uint32_t bl2[2] = {vl1[0], vl1[1]}, bl3[2] = {vl1[2], vl1[3]};
                float* o0 = o[4 * np]; float* o1 = o[4 * np + 1];
                float* o2 = o[4 * np + 2]; float* o3 = o[4 * np + 3];
                mma16816(o0, ph, bh0); mma16816(o1, ph, bh1);
                mma16816(o2, ph, bh2); mma16816(o3, ph, bh3);
                mma16816(o0, pl, bh0); mma16816(o1, pl, bh1);
                mma16816(o2, pl, bh2); mma16816(o3, pl, bh3);
                mma16816(o0, ph, bl0); mma16816(o1, ph, bl1);
                mma16816(o2, ph, bl2); mma16816(o3, ph, bl3);
            }
        }
    }

    // ---- epilogue: normalize, fp16, store [b][v][t][128] ----
    float rin[2] = {1.f / lrow[0], 1.f / lrow[1]};
#pragma unroll
    for (int nt = 0; nt < 16; ++nt) {
        int ch = nt * 8 + (lane & 3) * 2;
#pragma unroll
        for (int h = 0; h < 2; ++h) {
            int v = q0 + (lane >> 2) + h * 8;
            float f0 = o[nt][2 * h] * rin[h];
            float f1 = o[nt][2 * h + 1] * rin[h];
            __half2 hv = __floats2half2_rn(f0, f1);
            size_t ad = ((size_t)(b * 256 + v) * 64 + t) * 128 + ch;
            *(uint32_t*)(avh + ad) = *(uint32_t*)&hv;
        }
    }
}

// ---------------------------------------------------------------------------
extern "C" void kernel_launch(void* const* d_in, const int* in_sizes, int n_in,
                              void* d_out, int out_size) {
    const float* x     = (const float*)d_in[0];
    const float* wq    = (const float*)d_in[1];
    const float* wk    = (const float*)d_in[2];
    const float* wv    = (const float*)d_in[3];
    const float* wo    = (const float*)d_in[4];
    const float* sigma = (const float*)d_in[5];
    float* out = (float*)d_out;

    __half *xh, *xl, *avh, *w1h, *w2h;
    __nv_bfloat16 *qkvh, *qkvl;
    cudaGetSymbolAddress((void**)&xh,   g_xh);
    cudaGetSymbolAddress((void**)&xl,   g_xl);
    cudaGetSymbolAddress((void**)&qkvh, g_qkvh);
    cudaGetSymbolAddress((void**)&qkvl, g_qkvl);
    cudaGetSymbolAddress((void**)&avh,  g_avh);
    cudaGetSymbolAddress((void**)&w1h,  g_w1h);
    cudaGetSymbolAddress((void**)&w2h,  g_w2h);

    cudaFuncSetAttribute(split_x_k,
                         cudaFuncAttributeMaxDynamicSharedMemorySize, 66560);
    split_x_k<<<dim3(256, 8), 256, 66560>>>(x, xh, xl);

    pack_w1_k<<<(192 * 2304 + 255) / 256, 256>>>(wq, wk, wv);
    pack_w2_k<<<(256 * 1152 + 255) / 256, 256>>>(wo);

    {   // conv1: IC=256 (16 chunks), OCTOT=192, 2-pass, split-bf16 transposed out
        auto k = conv_mma<16, 192, true, true>;
        cudaFuncSetAttribute(k, cudaFuncAttributeMaxDynamicSharedMemorySize,
                             114944);
        k<<<dim3(3, 64, 8), 256, 114944>>>(xh, xl, w1h,
                                           qkvh, qkvl, nullptr, nullptr, nullptr);
    }

    cudaFuncSetAttribute(attn_kernel,
                         cudaFuncAttributeMaxDynamicSharedMemorySize, ATTN_SMEM);
    attn_kernel<<<dim3(T_, B_), 512, ATTN_SMEM>>>(qkvh, qkvl, avh);

    {   // conv2: IC=128 (8 chunks), OCTOT=256, 1-pass, fp32 out + residual
        auto k = conv_mma<8, 256, false, false>;
        cudaFuncSetAttribute(k, cudaFuncAttributeMaxDynamicSharedMemorySize,
                             76928);
        k<<<dim3(4, 64, 8), 256, 76928>>>(avh, nullptr, w2h,
                                          nullptr, nullptr, out, x, sigma);
    }
}

// round 11
// speedup vs baseline: 2.2811x; 1.3263x over previous
#include <cuda_runtime.h>
#include <cuda_bf16.h>
#include <cuda_fp16.h>
#include <cstdint>

#define B_   8
#define V_   256
#define T_   64

// ---------------------------------------------------------------------------
// Global scratch
// ---------------------------------------------------------------------------
__device__ __half g_xh[8ll * 256 * 64 * 256];            // [b][v][t][256ic] fp16
__device__ __nv_bfloat16 g_qkvh[8ll * 64 * 256 * 192];   // [b][t][v][192] bf16
__device__ __nv_bfloat16 g_qkvl[8ll * 64 * 256 * 192];
__device__ __half g_avh[8ll * 256 * 64 * 128];           // [b][v][t][128ic] fp16
__device__ __half g_w1h[192 * 2304];                     // [oc][chunk][tap][16] fp16
__device__ __half g_w2h[256 * 1152];

// ---------------------------------------------------------------------------
// Helpers
// ---------------------------------------------------------------------------
__device__ __forceinline__ uint32_t smem_u32(const void* p) {
    return (uint32_t)__cvta_generic_to_shared(p);
}
__device__ __forceinline__ uint32_t pack2bf(float f0, float f1) {
    __nv_bfloat162 h = __floats2bfloat162_rn(f0, f1);
    return *(uint32_t*)&h;
}
__device__ __forceinline__ void split2(float f0, float f1,
                                       uint32_t& hp, uint32_t& lp) {
    hp = pack2bf(f0, f1);
    float h0 = __uint_as_float(hp << 16);
    float h1 = __uint_as_float(hp & 0xFFFF0000u);
    lp = pack2bf(f0 - h0, f1 - h1);
}

#define LDMX4(r, a) \
    asm volatile("ldmatrix.sync.aligned.m8n8.x4.shared.b16 {%0,%1,%2,%3},[%4];" \
        : "=r"((r)[0]), "=r"((r)[1]), "=r"((r)[2]), "=r"((r)[3]) : "r"(a))
#define LDMX4T(r, a) \
    asm volatile("ldmatrix.sync.aligned.m8n8.x4.trans.shared.b16 {%0,%1,%2,%3},[%4];" \
        : "=r"((r)[0]), "=r"((r)[1]), "=r"((r)[2]), "=r"((r)[3]) : "r"(a))
#define CP16(dst, src, sz) \
    asm volatile("cp.async.cg.shared.global [%0], [%1], 16, %2;" \
                 :: "r"(dst), "l"(src), "r"(sz) : "memory")
#define CP_COMMIT() asm volatile("cp.async.commit_group;" ::: "memory")
#define CP_WAIT(n)  asm volatile("cp.async.wait_group %0;" :: "n"(n) : "memory")

__device__ __forceinline__ void mma16816(float* c, const uint32_t* a, const uint32_t* b) {
    asm volatile(
        "mma.sync.aligned.m16n8k16.row.col.f32.bf16.bf16.f32 "
        "{%0,%1,%2,%3},{%4,%5,%6,%7},{%8,%9},{%0,%1,%2,%3};"
        : "+f"(c[0]), "+f"(c[1]), "+f"(c[2]), "+f"(c[3])
        : "r"(a[0]), "r"(a[1]), "r"(a[2]), "r"(a[3]), "r"(b[0]), "r"(b[1]));
}
__device__ __forceinline__ void mma16816h(float* c, const uint32_t* a, const uint32_t* b) {
    asm volatile(
        "mma.sync.aligned.m16n8k16.row.col.f32.f16.f16.f32 "
        "{%0,%1,%2,%3},{%4,%5,%6,%7},{%8,%9},{%0,%1,%2,%3};"
        : "+f"(c[0]), "+f"(c[1]), "+f"(c[2]), "+f"(c[3])
        : "r"(a[0]), "r"(a[1]), "r"(a[2]), "r"(a[3]), "r"(b[0]), "r"(b[1]));
}

// ---------------------------------------------------------------------------
// split_x: x NCHW fp32 -> [b][y][t][256ic] fp16 (hi only)
// ---------------------------------------------------------------------------
__global__ void split_x_k(const float* __restrict__ x,
                          __half* __restrict__ xh) {
    extern __shared__ float s[];               // [256 ic][65]
    const int y = blockIdx.x, b = blockIdx.y, tid = threadIdx.x;
    for (int r = 0; r < 64; r++) {
        int idx = r * 256 + tid, ic = idx >> 6, t = idx & 63;
        s[ic * 65 + t] = x[(((size_t)b * 256 + ic) * 256 + y) * 64 + t];
    }
    __syncthreads();
    size_t ob = ((size_t)(b * 256 + y)) * 64 * 256;
    for (int r = 0; r < 32; r++) {
        int idx = r * 512 + tid * 2, t = idx >> 8, ic = idx & 255;
        __half2 h = __floats2half2_rn(s[ic * 65 + t], s[(ic + 1) * 65 + t]);
        *(uint32_t*)(xh + ob + (size_t)t * 256 + ic) = *(uint32_t*)&h;
    }
}

// ---------------------------------------------------------------------------
// Weight packing: w[oc][ic][3][3] fp32 -> [oc][icchunk][tap][16ic] fp16
// ---------------------------------------------------------------------------
__global__ void pack_w1_k(const float* __restrict__ wq,
                          const float* __restrict__ wk,
                          const float* __restrict__ wv) {
    int id = blockIdx.x * blockDim.x + threadIdx.x;
    if (id >= 192 * 2304) return;
    int oc = id / 2304, kp = id % 2304;
    int chunk = kp / 144, rem = kp % 144, tap = rem / 16, i = rem & 15;
    int ic = chunk * 16 + i;
    float v;
    if (oc < 32)       v = wq[(oc * 256 + ic) * 9 + tap];
    else if (oc < 64)  v = wk[((oc - 32) * 256 + ic) * 9 + tap];
    else               v = wv[((oc - 64) * 256 + ic) * 9 + tap];
    g_w1h[id] = __float2half_rn(v);
}

__global__ void pack_w2_k(const float* __restrict__ wo) {
    int id = blockIdx.x * blockDim.x + threadIdx.x;
    if (id >= 256 * 1152) return;
    int oc = id / 1152, kp = id % 1152;
    int chunk = kp / 144, rem = kp % 144, tap = rem / 16, i = rem & 15;
    int ic = chunk * 16 + i;
    g_w2h[id] = __float2half_rn(wo[(oc * 128 + ic) * 9 + tap]);
}

// ---------------------------------------------------------------------------
// conv3x3 via mma.sync fp16, single-pass (fp16 activations and weights).
// CTA: 256 thr (8 warps: 4 m x 2 n), 2 CTAs/SM. M=256 positions x N=64 oc.
// Chunk = 16 ic.  A and B double-buffered (cp.async).
// Patch: [6 rows][66 cols] pixels of 48B stride. B: [64 oc][304B stride].
// ---------------------------------------------------------------------------
#define B_BUF   19456          // one B buffer (64*304)
#define ABUF    19008          // one A buffer (6*66*48)
#define BH_O    38016          // B base (2*ABUF)
#define CONV_SMEM 76928        // BH_O + 2*B_BUF

template<int ICC, int OCTOT, bool TRANS>
__global__ __launch_bounds__(256, 2)
void conv_mma(const __half* __restrict__ inh,
              const __half* __restrict__ wh,
              __nv_bfloat16* __restrict__ outh,
              __nv_bfloat16* __restrict__ outl,
              float* __restrict__ out32,
              const float* __restrict__ resid,
              const float* __restrict__ sigma) {
    constexpr int IC = ICC * 16;
    extern __shared__ char sm[];

    const int tid  = threadIdx.x;
    const int lane = tid & 31;
    const int w    = tid >> 5;
    const int ocB  = blockIdx.x * 64;
    const int y0   = blockIdx.y * 4;
    const int b    = blockIdx.z;
    const int m0   = (w & 3) * 64;
    const int n0   = (w >> 2) * 32;
    const uint32_t su = smem_u32(sm);

    float acc[4][4][4];
#pragma unroll
    for (int i = 0; i < 4; i++)
#pragma unroll
        for (int j = 0; j < 4; j++)
#pragma unroll
            for (int e = 0; e < 4; e++) acc[i][j][e] = 0.f;

    auto stageA = [&](int c, int buf) {
        uint32_t au = su + buf * ABUF;
        for (int p = tid; p < 396; p += 256) {
            int row = p / 66, col = p - row * 66;
            int gy = y0 + row - 1, gt = col - 1;
            bool ok = ((unsigned)gy < 256u) && ((unsigned)gt < 64u);
            const __half* src = ok
                ? inh + ((size_t)((b * 256 + gy) * 64 + gt)) * IC + c * 16
                : inh;
            uint32_t dst = au + (uint32_t)(row * 66 + col) * 48;
            int sz = ok ? 16 : 0;
            CP16(dst, src, sz);
            CP16(dst + 16, src + 8, sz);
        }
    };
    auto stageB = [&](int c, int buf) {
        for (int i = tid; i < 1152; i += 256) {
            int n = i / 18, seg = i - n * 18;
            const __half* src = wh + ((size_t)(ocB + n) * ICC + c) * 144 + seg * 8;
            uint32_t dst = su + BH_O + buf * B_BUF + n * 304 + seg * 16;
            CP16(dst, src, 16);
        }
    };

    stageA(0, 0);
    stageB(0, 0);
    CP_COMMIT();

    const int l16 = lane & 15;
    const int bg   = lane >> 3;
    const int brow = (bg >> 1) * 8 + (lane & 7);
    const int bko  = (bg & 1) * 16;

    for (int c = 0; c < ICC; ++c) {
        if (c + 1 < ICC) {
            stageA(c + 1, (c + 1) & 1);
            stageB(c + 1, (c + 1) & 1);
            CP_COMMIT();
            CP_WAIT(1);
        } else {
            CP_WAIT(0);
        }
        __syncthreads();

        const uint32_t sa = su + (c & 1) * ABUF;
        const uint32_t sb = su + BH_O + (c & 1) * B_BUF;
#pragma unroll
        for (int tap = 0; tap < 9; ++tap) {
            const int ky = tap / 3, kx = tap - ky * 3;
            uint32_t bf0[4], bf1[4];
            {
                uint32_t ad = sb + (n0 + brow) * 304 + tap * 32 + bko;
                LDMX4(bf0, ad);
                LDMX4(bf1, ad + 16 * 304);
            }
#pragma unroll
            for (int mp = 0; mp < 2; ++mp) {
                uint32_t a0h[4], a1h[4];
                {
                    int mrow = m0 + (2 * mp) * 16 + l16;
                    int rp = (mrow >> 6) + ky, cp = (mrow & 63) + kx;
                    uint32_t ad = sa + (uint32_t)(rp * 66 + cp) * 48 + (lane >> 4) * 16;
                    LDMX4(a0h, ad);
                }
                {
                    int mrow = m0 + (2 * mp + 1) * 16 + l16;
                    int rp = (mrow >> 6) + ky, cp = (mrow & 63) + kx;
                    uint32_t ad = sa + (uint32_t)(rp * 66 + cp) * 48 + (lane >> 4) * 16;
                    LDMX4(a1h, ad);
                }
                mma16816h(acc[2 * mp][0],     a0h, &bf0[0]);
                mma16816h(acc[2 * mp][1],     a0h, &bf0[2]);
                mma16816h(acc[2 * mp][2],     a0h, &bf1[0]);
                mma16816h(acc[2 * mp][3],     a0h, &bf1[2]);
                mma16816h(acc[2 * mp + 1][0], a1h, &bf0[0]);
                mma16816h(acc[2 * mp + 1][1], a1h, &bf0[2]);
                mma16816h(acc[2 * mp + 1][2], a1h, &bf1[0]);
                mma16816h(acc[2 * mp + 1][3], a1h, &bf1[2]);
            }
        }
        __syncthreads();
    }

    // ---- epilogue ----
    const int r0l = lane >> 2, c0l = (lane & 3) * 2;
    if constexpr (TRANS) {
#pragma unroll
        for (int mt = 0; mt < 4; ++mt)
#pragma unroll
            for (int nt = 0; nt < 4; ++nt) {
                int oc = ocB + n0 + nt * 8 + c0l;
#pragma unroll
                for (int h = 0; h < 2; ++h) {
                    int m = m0 + mt * 16 + r0l + h * 8;
                    int v = y0 + (m >> 6), t = m & 63;
                    uint32_t hp, lp;
                    split2(acc[mt][nt][h * 2], acc[mt][nt][h * 2 + 1], hp, lp);
                    size_t base = ((size_t)((b * 64 + t) * 256 + v)) * OCTOT + oc;
                    *(uint32_t*)(outh + base) = hp;
                    *(uint32_t*)(outl + base) = lp;
                }
            }
    } else {
        float sg = sigma[0];
#pragma unroll
        for (int mt = 0; mt < 4; ++mt)
#pragma unroll
            for (int nt = 0; nt < 4; ++nt)
#pragma unroll
                for (int h = 0; h < 2; ++h) {
                    int m = m0 + mt * 16 + r0l + h * 8;
                    int v = y0 + (m >> 6), t = m & 63;
#pragma unroll
                    for (int e = 0; e < 2; ++e) {
                        int oc = ocB + n0 + nt * 8 + c0l + e;
                        size_t idx = (((size_t)b * OCTOT + oc) * 256 + v) * 64 + t;
                        out32[idx] = resid[idx] + sg * acc[mt][nt][h * 2 + e];
                    }
                }
    }
}

// ---------------------------------------------------------------------------
// Attention via mma.sync bf16 hi/lo (flash-style online softmax).
// Output: single fp16 [b][v][t][128] (conv2 is single-pass).
// ---------------------------------------------------------------------------
#define QH_O 0
#define QL_O 20480
#define KH_O 40960
#define KL_O 61440
#define VH_O 81920
#define VL_O 151552
#define ATTN_SMEM 221184

__global__ __launch_bounds__(512, 1)
void attn_kernel(const __nv_bfloat16* __restrict__ qh,
                 const __nv_bfloat16* __restrict__ ql,
                 __half* __restrict__ avh) {
    extern __shared__ char smc[];
    const int tid  = threadIdx.x;
    const int lane = tid & 31;
    const int w    = tid >> 5;
    const int t    = blockIdx.x;
    const int b    = blockIdx.y;
    const uint32_t su = smem_u32(smc);

    const size_t sbase = ((size_t)(b * 64 + t)) * 256 * 192;
    for (int idx = tid; idx < 12288; idx += 512) {
        int half = idx >= 6144;
        int r = half ? idx - 6144 : idx;
        int row = r / 24, seg = r - row * 24;
        float4 val = *(const float4*)((half ? ql : qh) + sbase + (size_t)row * 192 + seg * 8);
        uint32_t dst;
        if (seg < 4)       dst = (half ? QL_O : QH_O) + row * 80 + seg * 16;
        else if (seg < 8)  dst = (half ? KL_O : KH_O) + row * 80 + (seg - 4) * 16;
        else               dst = (half ? VL_O : VH_O) + row * 272 + (seg - 8) * 16;
        *(float4*)(smc + dst) = val;
    }
    __syncthreads();

    const int q0  = w * 16;
    const int l16 = lane & 15;

    float o[16][4];
#pragma unroll
    for (int i = 0; i < 16; i++)
#pragma unroll
        for (int j = 0; j < 4; j++) o[i][j] = 0.f;
    float mrow[2] = {-1e30f, -1e30f};
    float lrow[2] = {0.f, 0.f};

    for (int c0 = 0; c0 < 4; ++c0) {
        float s[8][4];
#pragma unroll
        for (int i = 0; i < 8; i++)
#pragma unroll
            for (int j = 0; j < 4; j++) s[i][j] = 0.f;

#pragma unroll
        for (int kk = 0; kk < 2; ++kk) {
            uint32_t aH[4], aL[4];
            uint32_t qa = su + QH_O + (q0 + l16) * 80 + (lane >> 4) * 16 + kk * 32;
            LDMX4(aH, qa);
            LDMX4(aL, qa + (QL_O - QH_O));
#pragma unroll
            for (int np = 0; np < 2; ++np) {
                uint32_t kh0[4], kl0[4], kh1[4], kl1[4];
                uint32_t ka0 = su + KH_O + (c0 * 64 + (2 * np) * 16 + l16) * 80
                             + (lane >> 4) * 16 + kk * 32;
                LDMX4(kh0, ka0);
                LDMX4(kl0, ka0 + (KL_O - KH_O));
                LDMX4(kh1, ka0 + 16 * 80);
                LDMX4(kl1, ka0 + 16 * 80 + (KL_O - KH_O));
                uint32_t b0h[2] = {kh0[0], kh0[2]}, b1h[2] = {kh0[1], kh0[3]};
                uint32_t b2h[2] = {kh1[0], kh1[2]}, b3h[2] = {kh1[1], kh1[3]};
                uint32_t b0l[2] = {kl0[0], kl0[2]}, b1l[2] = {kl0[1], kl0[3]};
                uint32_t b2l[2] = {kl1[0], kl1[2]}, b3l[2] = {kl1[1], kl1[3]};
                float* s0 = s[4 * np]; float* s1 = s[4 * np + 1];
                float* s2 = s[4 * np + 2]; float* s3 = s[4 * np + 3];
                mma16816(s0, aH, b0h); mma16816(s1, aH, b1h);
                mma16816(s2, aH, b2h); mma16816(s3, aH, b3h);
                mma16816(s0, aL, b0h); mma16816(s1, aL, b1h);
                mma16816(s2, aL, b2h); mma16816(s3, aL, b3h);
                mma16816(s0, aH, b0l); mma16816(s1, aH, b1l);
                mma16816(s2, aH, b2l); mma16816(s3, aH, b3l);
            }
        }

#pragma unroll
        for (int h = 0; h < 2; ++h) {
            float mc = -1e30f;
#pragma unroll
            for (int nt = 0; nt < 8; ++nt)
                mc = fmaxf(mc, fmaxf(s[nt][2 * h], s[nt][2 * h + 1]));
            mc = fmaxf(mc, __shfl_xor_sync(0xffffffffu, mc, 1));
            mc = fmaxf(mc, __shfl_xor_sync(0xffffffffu, mc, 2));
            float mn = fmaxf(mrow[h], mc);
            float sc = __expf(mrow[h] - mn);
            mrow[h] = mn;
            float ls = 0.f;
#pragma unroll
            for (int nt = 0; nt < 8; ++nt) {
                float p0 = __expf(s[nt][2 * h] - mn);
                float p1 = __expf(s[nt][2 * h + 1] - mn);
                s[nt][2 * h] = p0; s[nt][2 * h + 1] = p1;
                ls += p0 + p1;
            }
            ls += __shfl_xor_sync(0xffffffffu, ls, 1);
            ls += __shfl_xor_sync(0xffffffffu, ls, 2);
            lrow[h] = lrow[h] * sc + ls;
#pragma unroll
            for (int nt = 0; nt < 16; ++nt) {
                o[nt][2 * h]     *= sc;
                o[nt][2 * h + 1] *= sc;
            }
        }

#pragma unroll
        for (int kk = 0; kk < 4; ++kk) {
            uint32_t ph[4], pl[4];
            split2(s[2 * kk][0],     s[2 * kk][1],     ph[0], pl[0]);
            split2(s[2 * kk][2],     s[2 * kk][3],     ph[1], pl[1]);
            split2(s[2 * kk + 1][0], s[2 * kk + 1][1], ph[2], pl[2]);
            split2(s[2 * kk + 1][2], s[2 * kk + 1][3], ph[3], pl[3]);
#pragma unroll
            for (int np = 0; np < 4; ++np) {
                uint32_t vh0[4], vl0[4], vh1[4], vl1[4];
                uint32_t va = su + VH_O + (c0 * 64 + kk * 16 + l16) * 272
                            + (lane >> 4) * 16 + (2 * np) * 32;
                LDMX4T(vh0, va);
                LDMX4T(vl0, va + (VL_O - VH_O));
                LDMX4T(vh1, va + 32);
                LDMX4T(vl1, va + 32 + (VL_O - VH_O));
                uint32_t bh0[2] = {vh0[0], vh0[1]}, bh1[2] = {vh0[2], vh0[3]};
                uint32_t bh2[2] = {vh1[0], vh1[1]}, bh3[2] = {vh1[2], vh1[3]};
                uint32_t bl0[2] = {vl0[0], vl0[1]}, bl1[2] = {vl0[2], vl0[3]};
                uint32_t bl2[2] = {vl1[0], vl1[1]}, bl3[2] = {vl1[2], vl1[3]};
                float* o0 = o[4 * np]; float* o1 = o[4 * np + 1];
                float* o2 = o[4 * np + 2]; float* o3 = o[4 * np + 3];
                mma16816(o0, ph, bh0); mma16816(o1, ph, bh1);
                mma16816(o2, ph, bh2); mma16816(o3, ph, bh3);
                mma16816(o0, pl, bh0); mma16816(o1, pl, bh1);
                mma16816(o2, pl, bh2); mma16816(o3, pl, bh3);
                mma16816(o0, ph, bl0); mma16816(o1, ph, bl1);
                mma16816(o2, ph, bl2); mma16816(o3, ph, bl3);
            }
        }
    }

    // ---- epilogue: normalize, fp16, store [b][v][t][128] ----
    float rin[2] = {1.f / lrow[0], 1.f / lrow[1]};
#pragma unroll
    for (int nt = 0; nt < 16; ++nt) {
        int ch = nt * 8 + (lane & 3) * 2;
#pragma unroll
        for (int h = 0; h < 2; ++h) {
            int v = q0 + (lane >> 2) + h * 8;
            float f0 = o[nt][2 * h] * rin[h];
            float f1 = o[nt][2 * h + 1] * rin[h];
            __half2 hv = __floats2half2_rn(f0, f1);
            size_t ad = ((size_t)(b * 256 + v) * 64 + t) * 128 + ch;
            *(uint32_t*)(avh + ad) = *(uint32_t*)&hv;
        }
    }
}

// ---------------------------------------------------------------------------
extern "C" void kernel_launch(void* const* d_in, const int* in_sizes, int n_in,
                              void* d_out, int out_size) {
    const float* x     = (const float*)d_in[0];
    const float* wq    = (const float*)d_in[1];
    const float* wk    = (const float*)d_in[2];
    const float* wv    = (const float*)d_in[3];
    const float* wo    = (const float*)d_in[4];
    const float* sigma = (const float*)d_in[5];
    float* out = (float*)d_out;

    __half *xh, *avh, *w1h, *w2h;
    __nv_bfloat16 *qkvh, *qkvl;
    cudaGetSymbolAddress((void**)&xh,   g_xh);
    cudaGetSymbolAddress((void**)&qkvh, g_qkvh);
    cudaGetSymbolAddress((void**)&qkvl, g_qkvl);
    cudaGetSymbolAddress((void**)&avh,  g_avh);
    cudaGetSymbolAddress((void**)&w1h,  g_w1h);
    cudaGetSymbolAddress((void**)&w2h,  g_w2h);

    cudaFuncSetAttribute(split_x_k,
                         cudaFuncAttributeMaxDynamicSharedMemorySize, 66560);
    split_x_k<<<dim3(256, 8), 256, 66560>>>(x, xh);

    pack_w1_k<<<(192 * 2304 + 255) / 256, 256>>>(wq, wk, wv);
    pack_w2_k<<<(256 * 1152 + 255) / 256, 256>>>(wo);

    {   // conv1: IC=256 (16 chunks), OCTOT=192, 1-pass, split-bf16 transposed out
        auto k = conv_mma<16, 192, true>;
        cudaFuncSetAttribute(k, cudaFuncAttributeMaxDynamicSharedMemorySize,
                             CONV_SMEM);
        k<<<dim3(3, 64, 8), 256, CONV_SMEM>>>(xh, w1h,
                                              qkvh, qkvl, nullptr, nullptr, nullptr);
    }

    cudaFuncSetAttribute(attn_kernel,
                         cudaFuncAttributeMaxDynamicSharedMemorySize, ATTN_SMEM);
    attn_kernel<<<dim3(T_, B_), 512, ATTN_SMEM>>>(qkvh, qkvl, avh);

    {   // conv2: IC=128 (8 chunks), OCTOT=256, 1-pass, fp32 out + residual
        auto k = conv_mma<8, 256, false>;
        cudaFuncSetAttribute(k, cudaFuncAttributeMaxDynamicSharedMemorySize,
                             CONV_SMEM);
        k<<<dim3(4, 64, 8), 256, CONV_SMEM>>>(avh, w2h,
                                              nullptr, nullptr, out, x, sigma);
    }
}

// round 12
// speedup vs baseline: 2.5846x; 1.1331x over previous
#include <cuda_runtime.h>
#include <cuda_bf16.h>
#include <cuda_fp16.h>
#include <cstdint>

#define B_   8
#define V_   256
#define T_   64

// ---------------------------------------------------------------------------
// Global scratch
// ---------------------------------------------------------------------------
__device__ __half g_xh[8ll * 256 * 64 * 256];            // [b][v][t][256ic] fp16
__device__ __half g_qkv[8ll * 64 * 256 * 192];           // [b][t][v][192] fp16
__device__ __half g_avh[8ll * 256 * 64 * 128];           // [b][v][t][128ic] fp16
__device__ __half g_w1h[192 * 2304];                     // [oc][chunk][tap][16] fp16
__device__ __half g_w2h[256 * 1152];

// ---------------------------------------------------------------------------
// Helpers
// ---------------------------------------------------------------------------
__device__ __forceinline__ uint32_t smem_u32(const void* p) {
    return (uint32_t)__cvta_generic_to_shared(p);
}
__device__ __forceinline__ uint32_t pack2h(float f0, float f1) {
    __half2 h = __floats2half2_rn(f0, f1);
    return *(uint32_t*)&h;
}

#define LDMX4(r, a) \
    asm volatile("ldmatrix.sync.aligned.m8n8.x4.shared.b16 {%0,%1,%2,%3},[%4];" \
        : "=r"((r)[0]), "=r"((r)[1]), "=r"((r)[2]), "=r"((r)[3]) : "r"(a))
#define LDMX4T(r, a) \
    asm volatile("ldmatrix.sync.aligned.m8n8.x4.trans.shared.b16 {%0,%1,%2,%3},[%4];" \
        : "=r"((r)[0]), "=r"((r)[1]), "=r"((r)[2]), "=r"((r)[3]) : "r"(a))
#define CP16(dst, src, sz) \
    asm volatile("cp.async.cg.shared.global [%0], [%1], 16, %2;" \
                 :: "r"(dst), "l"(src), "r"(sz) : "memory")
#define CP_COMMIT() asm volatile("cp.async.commit_group;" ::: "memory")
#define CP_WAIT(n)  asm volatile("cp.async.wait_group %0;" :: "n"(n) : "memory")

__device__ __forceinline__ void mma16816h(float* c, const uint32_t* a, const uint32_t* b) {
    asm volatile(
        "mma.sync.aligned.m16n8k16.row.col.f32.f16.f16.f32 "
        "{%0,%1,%2,%3},{%4,%5,%6,%7},{%8,%9},{%0,%1,%2,%3};"
        : "+f"(c[0]), "+f"(c[1]), "+f"(c[2]), "+f"(c[3])
        : "r"(a[0]), "r"(a[1]), "r"(a[2]), "r"(a[3]), "r"(b[0]), "r"(b[1]));
}

// ---------------------------------------------------------------------------
// split_x: x NCHW fp32 -> [b][y][t][256ic] fp16
// ---------------------------------------------------------------------------
__global__ void split_x_k(const float* __restrict__ x,
                          __half* __restrict__ xh) {
    extern __shared__ float s[];               // [256 ic][65]
    const int y = blockIdx.x, b = blockIdx.y, tid = threadIdx.x;
    for (int r = 0; r < 64; r++) {
        int idx = r * 256 + tid, ic = idx >> 6, t = idx & 63;
        s[ic * 65 + t] = x[(((size_t)b * 256 + ic) * 256 + y) * 64 + t];
    }
    __syncthreads();
    size_t ob = ((size_t)(b * 256 + y)) * 64 * 256;
    for (int r = 0; r < 32; r++) {
        int idx = r * 512 + tid * 2, t = idx >> 8, ic = idx & 255;
        *(uint32_t*)(xh + ob + (size_t)t * 256 + ic)
            = pack2h(s[ic * 65 + t], s[(ic + 1) * 65 + t]);
    }
}

// ---------------------------------------------------------------------------
// Weight packing: w[oc][ic][3][3] fp32 -> [oc][icchunk][tap][16ic] fp16
// ---------------------------------------------------------------------------
__global__ void pack_w1_k(const float* __restrict__ wq,
                          const float* __restrict__ wk,
                          const float* __restrict__ wv) {
    int id = blockIdx.x * blockDim.x + threadIdx.x;
    if (id >= 192 * 2304) return;
    int oc = id / 2304, kp = id % 2304;
    int chunk = kp / 144, rem = kp % 144, tap = rem / 16, i = rem & 15;
    int ic = chunk * 16 + i;
    float v;
    if (oc < 32)       v = wq[(oc * 256 + ic) * 9 + tap];
    else if (oc < 64)  v = wk[((oc - 32) * 256 + ic) * 9 + tap];
    else               v = wv[((oc - 64) * 256 + ic) * 9 + tap];
    g_w1h[id] = __float2half_rn(v);
}

__global__ void pack_w2_k(const float* __restrict__ wo) {
    int id = blockIdx.x * blockDim.x + threadIdx.x;
    if (id >= 256 * 1152) return;
    int oc = id / 1152, kp = id % 1152;
    int chunk = kp / 144, rem = kp % 144, tap = rem / 16, i = rem & 15;
    int ic = chunk * 16 + i;
    g_w2h[id] = __float2half_rn(wo[(oc * 128 + ic) * 9 + tap]);
}

// ---------------------------------------------------------------------------
// conv3x3 via mma.sync fp16, single-pass.
// CTA: 256 thr (8 warps: 4 m x 2 n), 2 CTAs/SM. M=256 positions x N=64 oc.
// Chunk = 16 ic.  A and B double-buffered (cp.async).
// Patch: [6 rows][66 cols] pixels of 48B stride. B: [64 oc][304B stride].
// ---------------------------------------------------------------------------
#define B_BUF   19456          // one B buffer (64*304)
#define ABUF    19008          // one A buffer (6*66*48)
#define BH_O    38016          // B base (2*ABUF)
#define CONV_SMEM 76928        // BH_O + 2*B_BUF

template<int ICC, int OCTOT, bool TRANS>
__global__ __launch_bounds__(256, 2)
void conv_mma(const __half* __restrict__ inh,
              const __half* __restrict__ wh,
              __half* __restrict__ outh,
              float* __restrict__ out32,
              const float* __restrict__ resid,
              const float* __restrict__ sigma) {
    constexpr int IC = ICC * 16;
    extern __shared__ char sm[];

    const int tid  = threadIdx.x;
    const int lane = tid & 31;
    const int w    = tid >> 5;
    const int ocB  = blockIdx.x * 64;
    const int y0   = blockIdx.y * 4;
    const int b    = blockIdx.z;
    const int m0   = (w & 3) * 64;
    const int n0   = (w >> 2) * 32;
    const uint32_t su = smem_u32(sm);

    float acc[4][4][4];
#pragma unroll
    for (int i = 0; i < 4; i++)
#pragma unroll
        for (int j = 0; j < 4; j++)
#pragma unroll
            for (int e = 0; e < 4; e++) acc[i][j][e] = 0.f;

    auto stageA = [&](int c, int buf) {
        uint32_t au = su + buf * ABUF;
        for (int p = tid; p < 396; p += 256) {
            int row = p / 66, col = p - row * 66;
            int gy = y0 + row - 1, gt = col - 1;
            bool ok = ((unsigned)gy < 256u) && ((unsigned)gt < 64u);
            const __half* src = ok
                ? inh + ((size_t)((b * 256 + gy) * 64 + gt)) * IC + c * 16
                : inh;
            uint32_t dst = au + (uint32_t)(row * 66 + col) * 48;
            int sz = ok ? 16 : 0;
            CP16(dst, src, sz);
            CP16(dst + 16, src + 8, sz);
        }
    };
    auto stageB = [&](int c, int buf) {
        for (int i = tid; i < 1152; i += 256) {
            int n = i / 18, seg = i - n * 18;
            const __half* src = wh + ((size_t)(ocB + n) * ICC + c) * 144 + seg * 8;
            uint32_t dst = su + BH_O + buf * B_BUF + n * 304 + seg * 16;
            CP16(dst, src, 16);
        }
    };

    stageA(0, 0);
    stageB(0, 0);
    CP_COMMIT();

    const int l16 = lane & 15;
    const int bg   = lane >> 3;
    const int brow = (bg >> 1) * 8 + (lane & 7);
    const int bko  = (bg & 1) * 16;

    for (int c = 0; c < ICC; ++c) {
        if (c + 1 < ICC) {
            stageA(c + 1, (c + 1) & 1);
            stageB(c + 1, (c + 1) & 1);
            CP_COMMIT();
            CP_WAIT(1);
        } else {
            CP_WAIT(0);
        }
        __syncthreads();

        const uint32_t sa = su + (c & 1) * ABUF;
        const uint32_t sb = su + BH_O + (c & 1) * B_BUF;
#pragma unroll
        for (int tap = 0; tap < 9; ++tap) {
            const int ky = tap / 3, kx = tap - ky * 3;
            uint32_t bf0[4], bf1[4];
            {
                uint32_t ad = sb + (n0 + brow) * 304 + tap * 32 + bko;
                LDMX4(bf0, ad);
                LDMX4(bf1, ad + 16 * 304);
            }
#pragma unroll
            for (int mp = 0; mp < 2; ++mp) {
                uint32_t a0h[4], a1h[4];
                {
                    int mrow = m0 + (2 * mp) * 16 + l16;
                    int rp = (mrow >> 6) + ky, cp = (mrow & 63) + kx;
                    uint32_t ad = sa + (uint32_t)(rp * 66 + cp) * 48 + (lane >> 4) * 16;
                    LDMX4(a0h, ad);
                }
                {
                    int mrow = m0 + (2 * mp + 1) * 16 + l16;
                    int rp = (mrow >> 6) + ky, cp = (mrow & 63) + kx;
                    uint32_t ad = sa + (uint32_t)(rp * 66 + cp) * 48 + (lane >> 4) * 16;
                    LDMX4(a1h, ad);
                }
                mma16816h(acc[2 * mp][0],     a0h, &bf0[0]);
                mma16816h(acc[2 * mp][1],     a0h, &bf0[2]);
                mma16816h(acc[2 * mp][2],     a0h, &bf1[0]);
                mma16816h(acc[2 * mp][3],     a0h, &bf1[2]);
                mma16816h(acc[2 * mp + 1][0], a1h, &bf0[0]);
                mma16816h(acc[2 * mp + 1][1], a1h, &bf0[2]);
                mma16816h(acc[2 * mp + 1][2], a1h, &bf1[0]);
                mma16816h(acc[2 * mp + 1][3], a1h, &bf1[2]);
            }
        }
        __syncthreads();
    }

    // ---- epilogue ----
    const int r0l = lane >> 2, c0l = (lane & 3) * 2;
    if constexpr (TRANS) {
#pragma unroll
        for (int mt = 0; mt < 4; ++mt)
#pragma unroll
            for (int nt = 0; nt < 4; ++nt) {
                int oc = ocB + n0 + nt * 8 + c0l;
#pragma unroll
                for (int h = 0; h < 2; ++h) {
                    int m = m0 + mt * 16 + r0l + h * 8;
                    int v = y0 + (m >> 6), t = m & 63;
                    size_t base = ((size_t)((b * 64 + t) * 256 + v)) * OCTOT + oc;
                    *(uint32_t*)(outh + base)
                        = pack2h(acc[mt][nt][h * 2], acc[mt][nt][h * 2 + 1]);
                }
            }
    } else {
        float sg = sigma[0];
#pragma unroll
        for (int mt = 0; mt < 4; ++mt)
#pragma unroll
            for (int nt = 0; nt < 4; ++nt)
#pragma unroll
                for (int h = 0; h < 2; ++h) {
                    int m = m0 + mt * 16 + r0l + h * 8;
                    int v = y0 + (m >> 6), t = m & 63;
#pragma unroll
                    for (int e = 0; e < 2; ++e) {
                        int oc = ocB + n0 + nt * 8 + c0l + e;
                        size_t idx = (((size_t)b * OCTOT + oc) * 256 + v) * 64 + t;
                        out32[idx] = resid[idx] + sg * acc[mt][nt][h * 2 + e];
                    }
                }
    }
}

// ---------------------------------------------------------------------------
// Attention, all-fp16 single-pass mma (flash-style online softmax, fp32 accum).
// One CTA per (b,t): 512 thr, 16 warps, warp owns 16 query rows.
// SMEM: Q [256 x 80B], K [256 x 80B], V [256 x 272B]  (fp16).
// 4 key chunks of 64.  Output fp16 [b][v][t][128].
// ---------------------------------------------------------------------------
#define QH_O 0
#define KH_O 20480
#define VH_O 40960
#define ATTN_SMEM 110592

__global__ __launch_bounds__(512, 1)
void attn_kernel(const __half* __restrict__ qkv,
                 __half* __restrict__ avh) {
    extern __shared__ char smc[];
    const int tid  = threadIdx.x;
    const int lane = tid & 31;
    const int w    = tid >> 5;
    const int t    = blockIdx.x;
    const int b    = blockIdx.y;
    const uint32_t su = smem_u32(smc);

    // ---- load slice [256 rows][192 ch] fp16 into Q/K/V smem ----
    const size_t sbase = ((size_t)(b * 64 + t)) * 256 * 192;
    for (int idx = tid; idx < 6144; idx += 512) {
        int row = idx / 24, seg = idx % 24;
        float4 val = *(const float4*)(qkv + sbase + (size_t)row * 192 + seg * 8);
        uint32_t dst;
        if (seg < 4)       dst = QH_O + row * 80 + seg * 16;
        else if (seg < 8)  dst = KH_O + row * 80 + (seg - 4) * 16;
        else               dst = VH_O + row * 272 + (seg - 8) * 16;
        *(float4*)(smc + dst) = val;
    }
    __syncthreads();

    const int q0  = w * 16;
    const int l16 = lane & 15;

    float o[16][4];
#pragma unroll
    for (int i = 0; i < 16; i++)
#pragma unroll
        for (int j = 0; j < 4; j++) o[i][j] = 0.f;
    float mrow[2] = {-1e30f, -1e30f};
    float lrow[2] = {0.f, 0.f};

    for (int c0 = 0; c0 < 4; ++c0) {
        // ---- S = Q K^T (chunk of 64 keys), fp16 single-pass ----
        float s[8][4];
#pragma unroll
        for (int i = 0; i < 8; i++)
#pragma unroll
            for (int j = 0; j < 4; j++) s[i][j] = 0.f;

#pragma unroll
        for (int kk = 0; kk < 2; ++kk) {
            uint32_t aH[4];
            uint32_t qa = su + QH_O + (q0 + l16) * 80 + (lane >> 4) * 16 + kk * 32;
            LDMX4(aH, qa);
#pragma unroll
            for (int np = 0; np < 2; ++np) {
                uint32_t kh0[4], kh1[4];
                uint32_t ka0 = su + KH_O + (c0 * 64 + (2 * np) * 16 + l16) * 80
                             + (lane >> 4) * 16 + kk * 32;
                LDMX4(kh0, ka0);
                LDMX4(kh1, ka0 + 16 * 80);
                uint32_t b0h[2] = {kh0[0], kh0[2]}, b1h[2] = {kh0[1], kh0[3]};
                uint32_t b2h[2] = {kh1[0], kh1[2]}, b3h[2] = {kh1[1], kh1[3]};
                mma16816h(s[4 * np],     aH, b0h);
                mma16816h(s[4 * np + 1], aH, b1h);
                mma16816h(s[4 * np + 2], aH, b2h);
                mma16816h(s[4 * np + 3], aH, b3h);
            }
        }

        // ---- online softmax update ----
#pragma unroll
        for (int h = 0; h < 2; ++h) {
            float mc = -1e30f;
#pragma unroll
            for (int nt = 0; nt < 8; ++nt)
                mc = fmaxf(mc, fmaxf(s[nt][2 * h], s[nt][2 * h + 1]));
            mc = fmaxf(mc, __shfl_xor_sync(0xffffffffu, mc, 1));
            mc = fmaxf(mc, __shfl_xor_sync(0xffffffffu, mc, 2));
            float mn = fmaxf(mrow[h], mc);
            float sc = __expf(mrow[h] - mn);
            mrow[h] = mn;
            float ls = 0.f;
#pragma unroll
            for (int nt = 0; nt < 8; ++nt) {
                float p0 = __expf(s[nt][2 * h] - mn);
                float p1 = __expf(s[nt][2 * h + 1] - mn);
                s[nt][2 * h] = p0; s[nt][2 * h + 1] = p1;
                ls += p0 + p1;
            }
            ls += __shfl_xor_sync(0xffffffffu, ls, 1);
            ls += __shfl_xor_sync(0xffffffffu, ls, 2);
            lrow[h] = lrow[h] * sc + ls;
#pragma unroll
            for (int nt = 0; nt < 16; ++nt) {
                o[nt][2 * h]     *= sc;
                o[nt][2 * h + 1] *= sc;
            }
        }

        // ---- O += P V, fp16 single-pass ----
#pragma unroll
        for (int kk = 0; kk < 4; ++kk) {
            uint32_t ph[4];
            ph[0] = pack2h(s[2 * kk][0],     s[2 * kk][1]);
            ph[1] = pack2h(s[2 * kk][2],     s[2 * kk][3]);
            ph[2] = pack2h(s[2 * kk + 1][0], s[2 * kk + 1][1]);
            ph[3] = pack2h(s[2 * kk + 1][2], s[2 * kk + 1][3]);
#pragma unroll
            for (int np = 0; np < 4; ++np) {
                uint32_t vh0[4], vh1[4];
                uint32_t va = su + VH_O + (c0 * 64 + kk * 16 + l16) * 272
                            + (lane >> 4) * 16 + (2 * np) * 32;
                LDMX4T(vh0, va);
                LDMX4T(vh1, va + 32);
                uint32_t bh0[2] = {vh0[0], vh0[1]}, bh1[2] = {vh0[2], vh0[3]};
                uint32_t bh2[2] = {vh1[0], vh1[1]}, bh3[2] = {vh1[2], vh1[3]};
                mma16816h(o[4 * np],     ph, bh0);
                mma16816h(o[4 * np + 1], ph, bh1);
                mma16816h(o[4 * np + 2], ph, bh2);
                mma16816h(o[4 * np + 3], ph, bh3);
            }
        }
    }

    // ---- epilogue: normalize, fp16, store [b][v][t][128] ----
    float rin[2] = {1.f / lrow[0], 1.f / lrow[1]};
#pragma unroll
    for (int nt = 0; nt < 16; ++nt) {
        int ch = nt * 8 + (lane & 3) * 2;
#pragma unroll
        for (int h = 0; h < 2; ++h) {
            int v = q0 + (lane >> 2) + h * 8;
            size_t ad = ((size_t)(b * 256 + v) * 64 + t) * 128 + ch;
            *(uint32_t*)(avh + ad)
                = pack2h(o[nt][2 * h] * rin[h], o[nt][2 * h + 1] * rin[h]);
        }
    }
}

// ---------------------------------------------------------------------------
extern "C" void kernel_launch(void* const* d_in, const int* in_sizes, int n_in,
                              void* d_out, int out_size) {
    const float* x     = (const float*)d_in[0];
    const float* wq    = (const float*)d_in[1];
    const float* wk    = (const float*)d_in[2];
    const float* wv    = (const float*)d_in[3];
    const float* wo    = (const float*)d_in[4];
    const float* sigma = (const float*)d_in[5];
    float* out = (float*)d_out;

    __half *xh, *qkv, *avh, *w1h, *w2h;
    cudaGetSymbolAddress((void**)&xh,   g_xh);
    cudaGetSymbolAddress((void**)&qkv,  g_qkv);
    cudaGetSymbolAddress((void**)&avh,  g_avh);
    cudaGetSymbolAddress((void**)&w1h,  g_w1h);
    cudaGetSymbolAddress((void**)&w2h,  g_w2h);

    cudaFuncSetAttribute(split_x_k,
                         cudaFuncAttributeMaxDynamicSharedMemorySize, 66560);
    split_x_k<<<dim3(256, 8), 256, 66560>>>(x, xh);

    pack_w1_k<<<(192 * 2304 + 255) / 256, 256>>>(wq, wk, wv);
    pack_w2_k<<<(256 * 1152 + 255) / 256, 256>>>(wo);

    {   // conv1: IC=256 (16 chunks), OCTOT=192, fp16 transposed output
        auto k = conv_mma<16, 192, true>;
        cudaFuncSetAttribute(k, cudaFuncAttributeMaxDynamicSharedMemorySize,
                             CONV_SMEM);
        k<<<dim3(3, 64, 8), 256, CONV_SMEM>>>(xh, w1h,
                                              qkv, nullptr, nullptr, nullptr);
    }

    cudaFuncSetAttribute(attn_kernel,
                         cudaFuncAttributeMaxDynamicSharedMemorySize, ATTN_SMEM);
    attn_kernel<<<dim3(T_, B_), 512, ATTN_SMEM>>>(qkv, avh);

    {   // conv2: IC=128 (8 chunks), OCTOT=256, fp32 out + residual
        auto k = conv_mma<8, 256, false>;
        cudaFuncSetAttribute(k, cudaFuncAttributeMaxDynamicSharedMemorySize,
                             CONV_SMEM);
        k<<<dim3(4, 64, 8), 256, CONV_SMEM>>>(avh, w2h,
                                              nullptr, out, x, sigma);
    }
}

// round 13
// speedup vs baseline: 2.5952x; 1.0041x over previous
#include <cuda_runtime.h>
#include <cuda_bf16.h>
#include <cuda_fp16.h>
#include <cstdint>

#define B_   8
#define V_   256
#define T_   64

// ---------------------------------------------------------------------------
// Global scratch
// ---------------------------------------------------------------------------
__device__ __half g_xh[8ll * 256 * 64 * 256];            // [b][v][t][256ic] fp16
__device__ __half g_qkv[8ll * 64 * 256 * 192];           // [b][t][v][192] fp16
__device__ __half g_avh[8ll * 256 * 64 * 128];           // [b][v][t][128ic] fp16
__device__ __half g_w1h[192 * 2304];                     // [oc][chunk32][tap][32] fp16
__device__ __half g_w2h[256 * 1152];

// ---------------------------------------------------------------------------
// Helpers
// ---------------------------------------------------------------------------
__device__ __forceinline__ uint32_t smem_u32(const void* p) {
    return (uint32_t)__cvta_generic_to_shared(p);
}
__device__ __forceinline__ uint32_t pack2h(float f0, float f1) {
    __half2 h = __floats2half2_rn(f0, f1);
    return *(uint32_t*)&h;
}

#define LDMX4(r, a) \
    asm volatile("ldmatrix.sync.aligned.m8n8.x4.shared.b16 {%0,%1,%2,%3},[%4];" \
        : "=r"((r)[0]), "=r"((r)[1]), "=r"((r)[2]), "=r"((r)[3]) : "r"(a))
#define LDMX4T(r, a) \
    asm volatile("ldmatrix.sync.aligned.m8n8.x4.trans.shared.b16 {%0,%1,%2,%3},[%4];" \
        : "=r"((r)[0]), "=r"((r)[1]), "=r"((r)[2]), "=r"((r)[3]) : "r"(a))
#define CP16(dst, src, sz) \
    asm volatile("cp.async.cg.shared.global [%0], [%1], 16, %2;" \
                 :: "r"(dst), "l"(src), "r"(sz) : "memory")
#define CP_COMMIT() asm volatile("cp.async.commit_group;" ::: "memory")
#define CP_WAIT(n)  asm volatile("cp.async.wait_group %0;" :: "n"(n) : "memory")

__device__ __forceinline__ void mma16816h(float* c, const uint32_t* a, const uint32_t* b) {
    asm volatile(
        "mma.sync.aligned.m16n8k16.row.col.f32.f16.f16.f32 "
        "{%0,%1,%2,%3},{%4,%5,%6,%7},{%8,%9},{%0,%1,%2,%3};"
        : "+f"(c[0]), "+f"(c[1]), "+f"(c[2]), "+f"(c[3])
        : "r"(a[0]), "r"(a[1]), "r"(a[2]), "r"(a[3]), "r"(b[0]), "r"(b[1]));
}

// ---------------------------------------------------------------------------
// Merged prep kernel:
//   blocks [0, 2048):        split_x   (x NCHW fp32 -> [b][y][t][256ic] fp16)
//   blocks [2048, 3776):     pack_w1   ([oc][ic][3][3] -> [oc][chunk32][tap][32])
//   blocks [3776, 4928):     pack_w2
// ---------------------------------------------------------------------------
__global__ void prep_k(const float* __restrict__ x,
                       const float* __restrict__ wq,
                       const float* __restrict__ wk,
                       const float* __restrict__ wv,
                       const float* __restrict__ wo,
                       __half* __restrict__ xh,
                       __half* __restrict__ w1h,
                       __half* __restrict__ w2h) {
    const int bid = blockIdx.x, tid = threadIdx.x;
    if (bid < 2048) {
        extern __shared__ float s[];               // [256 ic][65]
        const int y = bid & 255, b = bid >> 8;
        for (int r = 0; r < 64; r++) {
            int idx = r * 256 + tid, ic = idx >> 6, t = idx & 63;
            s[ic * 65 + t] = x[(((size_t)b * 256 + ic) * 256 + y) * 64 + t];
        }
        __syncthreads();
        size_t ob = ((size_t)(b * 256 + y)) * 64 * 256;
        for (int r = 0; r < 32; r++) {
            int idx = r * 512 + tid * 2, t = idx >> 8, ic = idx & 255;
            *(uint32_t*)(xh + ob + (size_t)t * 256 + ic)
                = pack2h(s[ic * 65 + t], s[(ic + 1) * 65 + t]);
        }
    } else if (bid < 3776) {
        int id = (bid - 2048) * 256 + tid;          // 192*2304
        int oc = id / 2304, kp = id % 2304;
        int chunk = kp / 288, rem = kp % 288, tap = rem / 32, i = rem & 31;
        int ic = chunk * 32 + i;
        float v;
        if (oc < 32)       v = wq[(oc * 256 + ic) * 9 + tap];
        else if (oc < 64)  v = wk[((oc - 32) * 256 + ic) * 9 + tap];
        else               v = wv[((oc - 64) * 256 + ic) * 9 + tap];
        w1h[id] = __float2half_rn(v);
    } else {
        int id = (bid - 3776) * 256 + tid;          // 256*1152
        int oc = id / 1152, kp = id % 1152;
        int chunk = kp / 288, rem = kp % 288, tap = rem / 32, i = rem & 31;
        int ic = chunk * 32 + i;
        w2h[id] = __float2half_rn(wo[(oc * 128 + ic) * 9 + tap]);
    }
}

// ---------------------------------------------------------------------------
// conv3x3 via mma.sync fp16, single-pass, 32-ic chunks.
// CTA: 256 thr (8 warps: 4 m x 2 n), 2 CTAs/SM. M=256 positions x N=64 oc.
// A double-buffered, B single-buffered (cp.async).
// Patch: [6 rows][66 cols] pixels of 80B stride (64B = 32 ic payload).
// B: [64 oc][592B stride: 9 taps x 32 ic = 576B payload].
// Commit scheme per chunk c: [B_c][A_{c+1}] groups, CP_WAIT(1)
//   -> B(c) + A(c) complete, A(c+1) in flight.
// ---------------------------------------------------------------------------
#define ABUF    31680          // one A buffer (6*66*80)
#define BH_O    63360          // B base (2*ABUF)
#define CONV_SMEM 101248       // BH_O + 64*592

template<int ICC, int OCTOT, bool TRANS>
__global__ __launch_bounds__(256, 2)
void conv_mma(const __half* __restrict__ inh,
              const __half* __restrict__ wh,
              __half* __restrict__ outh,
              float* __restrict__ out32,
              const float* __restrict__ resid,
              const float* __restrict__ sigma) {
    constexpr int IC = ICC * 32;
    extern __shared__ char sm[];

    const int tid  = threadIdx.x;
    const int lane = tid & 31;
    const int w    = tid >> 5;
    const int ocB  = blockIdx.x * 64;
    const int y0   = blockIdx.y * 4;
    const int b    = blockIdx.z;
    const int m0   = (w & 3) * 64;
    const int n0   = (w >> 2) * 32;
    const uint32_t su = smem_u32(sm);

    float acc[4][4][4];
#pragma unroll
    for (int i = 0; i < 4; i++)
#pragma unroll
        for (int j = 0; j < 4; j++)
#pragma unroll
            for (int e = 0; e < 4; e++) acc[i][j][e] = 0.f;

    // stage A patch for 32-ic chunk c: 6x66 pixels, 64B each (4 x CP16)
    auto stageA = [&](int c, int buf) {
        uint32_t au = su + buf * ABUF;
        for (int p = tid; p < 396; p += 256) {
            int row = p / 66, col = p - row * 66;
            int gy = y0 + row - 1, gt = col - 1;
            bool ok = ((unsigned)gy < 256u) && ((unsigned)gt < 64u);
            const __half* src = ok
                ? inh + ((size_t)((b * 256 + gy) * 64 + gt)) * IC + c * 32
                : inh;
            uint32_t dst = au + (uint32_t)p * 80;
            int sz = ok ? 16 : 0;
            CP16(dst,      src,      sz);
            CP16(dst + 16, src + 8,  sz);
            CP16(dst + 32, src + 16, sz);
            CP16(dst + 48, src + 24, sz);
        }
    };
    // stage B for 32-ic chunk c (single buffer): 64 oc x 36 segs of 16B
    auto stageB = [&](int c) {
        for (int i = tid; i < 2304; i += 256) {
            int n = i / 36, seg = i - n * 36;
            const __half* src = wh + ((size_t)(ocB + n) * ICC + c) * 288 + seg * 8;
            uint32_t dst = su + BH_O + n * 592 + seg * 16;
            CP16(dst, src, 16);
        }
    };

    stageA(0, 0);
    CP_COMMIT();

    const int l16 = lane & 15;
    const int bg   = lane >> 3;
    const int brow = (bg >> 1) * 8 + (lane & 7);
    const int bko  = (bg & 1) * 16;

    for (int c = 0; c < ICC; ++c) {
        stageB(c);
        CP_COMMIT();
        if (c + 1 < ICC) {
            stageA(c + 1, (c + 1) & 1);
            CP_COMMIT();
            CP_WAIT(1);        // B(c)+A(c) done; A(c+1) in flight
        } else {
            CP_WAIT(0);
        }
        __syncthreads();

        const uint32_t sa = su + (c & 1) * ABUF;
        const uint32_t sb = su + BH_O;
#pragma unroll
        for (int tap = 0; tap < 9; ++tap) {
            const int ky = tap / 3, kx = tap - ky * 3;
#pragma unroll
            for (int kk = 0; kk < 2; ++kk) {
                uint32_t bf0[4], bf1[4];
                {
                    uint32_t ad = sb + (n0 + brow) * 592 + tap * 64 + kk * 32 + bko;
                    LDMX4(bf0, ad);
                    LDMX4(bf1, ad + 16 * 592);
                }
#pragma unroll
                for (int mp = 0; mp < 2; ++mp) {
                    uint32_t a0h[4], a1h[4];
                    {
                        int mrow = m0 + (2 * mp) * 16 + l16;
                        int rp = (mrow >> 6) + ky, cp = (mrow & 63) + kx;
                        uint32_t ad = sa + (uint32_t)(rp * 66 + cp) * 80
                                    + (lane >> 4) * 16 + kk * 32;
                        LDMX4(a0h, ad);
                    }
                    {
                        int mrow = m0 + (2 * mp + 1) * 16 + l16;
                        int rp = (mrow >> 6) + ky, cp = (mrow & 63) + kx;
                        uint32_t ad = sa + (uint32_t)(rp * 66 + cp) * 80
                                    + (lane >> 4) * 16 + kk * 32;
                        LDMX4(a1h, ad);
                    }
                    mma16816h(acc[2 * mp][0],     a0h, &bf0[0]);
                    mma16816h(acc[2 * mp][1],     a0h, &bf0[2]);
                    mma16816h(acc[2 * mp][2],     a0h, &bf1[0]);
                    mma16816h(acc[2 * mp][3],     a0h, &bf1[2]);
                    mma16816h(acc[2 * mp + 1][0], a1h, &bf0[0]);
                    mma16816h(acc[2 * mp + 1][1], a1h, &bf0[2]);
                    mma16816h(acc[2 * mp + 1][2], a1h, &bf1[0]);
                    mma16816h(acc[2 * mp + 1][3], a1h, &bf1[2]);
                }
            }
        }
        __syncthreads();       // protect B buffer + A buffer reuse
    }

    // ---- epilogue ----
    const int r0l = lane >> 2, c0l = (lane & 3) * 2;
    if constexpr (TRANS) {
#pragma unroll
        for (int mt = 0; mt < 4; ++mt)
#pragma unroll
            for (int nt = 0; nt < 4; ++nt) {
                int oc = ocB + n0 + nt * 8 + c0l;
#pragma unroll
                for (int h = 0; h < 2; ++h) {
                    int m = m0 + mt * 16 + r0l + h * 8;
                    int v = y0 + (m >> 6), t = m & 63;
                    size_t base = ((size_t)((b * 64 + t) * 256 + v)) * OCTOT + oc;
                    *(uint32_t*)(outh + base)
                        = pack2h(acc[mt][nt][h * 2], acc[mt][nt][h * 2 + 1]);
                }
            }
    } else {
        float sg = sigma[0];
#pragma unroll
        for (int mt = 0; mt < 4; ++mt)
#pragma unroll
            for (int nt = 0; nt < 4; ++nt)
#pragma unroll
                for (int h = 0; h < 2; ++h) {
                    int m = m0 + mt * 16 + r0l + h * 8;
                    int v = y0 + (m >> 6), t = m & 63;
#pragma unroll
                    for (int e = 0; e < 2; ++e) {
                        int oc = ocB + n0 + nt * 8 + c0l + e;
                        size_t idx = (((size_t)b * OCTOT + oc) * 256 + v) * 64 + t;
                        out32[idx] = resid[idx] + sg * acc[mt][nt][h * 2 + e];
                    }
                }
    }
}

// ---------------------------------------------------------------------------
// Attention, all-fp16 single-pass mma (flash-style online softmax, fp32 accum).
// One CTA per (b,t): 512 thr, 16 warps, warp owns 16 query rows.
// SMEM: Q [256 x 80B], K [256 x 80B], V [256 x 272B]  (fp16).
// ---------------------------------------------------------------------------
#define QH_O 0
#define KH_O 20480
#define VH_O 40960
#define ATTN_SMEM 110592

__global__ __launch_bounds__(512, 1)
void attn_kernel(const __half* __restrict__ qkv,
                 __half* __restrict__ avh) {
    extern __shared__ char smc[];
    const int tid  = threadIdx.x;
    const int lane = tid & 31;
    const int w    = tid >> 5;
    const int t    = blockIdx.x;
    const int b    = blockIdx.y;
    const uint32_t su = smem_u32(smc);

    const size_t sbase = ((size_t)(b * 64 + t)) * 256 * 192;
    for (int idx = tid; idx < 6144; idx += 512) {
        int row = idx / 24, seg = idx % 24;
        float4 val = *(const float4*)(qkv + sbase + (size_t)row * 192 + seg * 8);
        uint32_t dst;
        if (seg < 4)       dst = QH_O + row * 80 + seg * 16;
        else if (seg < 8)  dst = KH_O + row * 80 + (seg - 4) * 16;
        else               dst = VH_O + row * 272 + (seg - 8) * 16;
        *(float4*)(smc + dst) = val;
    }
    __syncthreads();

    const int q0  = w * 16;
    const int l16 = lane & 15;

    float o[16][4];
#pragma unroll
    for (int i = 0; i < 16; i++)
#pragma unroll
        for (int j = 0; j < 4; j++) o[i][j] = 0.f;
    float mrow[2] = {-1e30f, -1e30f};
    float lrow[2] = {0.f, 0.f};

    for (int c0 = 0; c0 < 4; ++c0) {
        float s[8][4];
#pragma unroll
        for (int i = 0; i < 8; i++)
#pragma unroll
            for (int j = 0; j < 4; j++) s[i][j] = 0.f;

#pragma unroll
        for (int kk = 0; kk < 2; ++kk) {
            uint32_t aH[4];
            uint32_t qa = su + QH_O + (q0 + l16) * 80 + (lane >> 4) * 16 + kk * 32;
            LDMX4(aH, qa);
#pragma unroll
            for (int np = 0; np < 2; ++np) {
                uint32_t kh0[4], kh1[4];
                uint32_t ka0 = su + KH_O + (c0 * 64 + (2 * np) * 16 + l16) * 80
                             + (lane >> 4) * 16 + kk * 32;
                LDMX4(kh0, ka0);
                LDMX4(kh1, ka0 + 16 * 80);
                uint32_t b0h[2] = {kh0[0], kh0[2]}, b1h[2] = {kh0[1], kh0[3]};
                uint32_t b2h[2] = {kh1[0], kh1[2]}, b3h[2] = {kh1[1], kh1[3]};
                mma16816h(s[4 * np],     aH, b0h);
                mma16816h(s[4 * np + 1], aH, b1h);
                mma16816h(s[4 * np + 2], aH, b2h);
                mma16816h(s[4 * np + 3], aH, b3h);
            }
        }

#pragma unroll
        for (int h = 0; h < 2; ++h) {
            float mc = -1e30f;
#pragma unroll
            for (int nt = 0; nt < 8; ++nt)
                mc = fmaxf(mc, fmaxf(s[nt][2 * h], s[nt][2 * h + 1]));
            mc = fmaxf(mc, __shfl_xor_sync(0xffffffffu, mc, 1));
            mc = fmaxf(mc, __shfl_xor_sync(0xffffffffu, mc, 2));
            float mn = fmaxf(mrow[h], mc);
            float sc = __expf(mrow[h] - mn);
            mrow[h] = mn;
            float ls = 0.f;
#pragma unroll
            for (int nt = 0; nt < 8; ++nt) {
                float p0 = __expf(s[nt][2 * h] - mn);
                float p1 = __expf(s[nt][2 * h + 1] - mn);
                s[nt][2 * h] = p0; s[nt][2 * h + 1] = p1;
                ls += p0 + p1;
            }
            ls += __shfl_xor_sync(0xffffffffu, ls, 1);
            ls += __shfl_xor_sync(0xffffffffu, ls, 2);
            lrow[h] = lrow[h] * sc + ls;
#pragma unroll
            for (int nt = 0; nt < 16; ++nt) {
                o[nt][2 * h]     *= sc;
                o[nt][2 * h + 1] *= sc;
            }
        }

#pragma unroll
        for (int kk = 0; kk < 4; ++kk) {
            uint32_t ph[4];
            ph[0] = pack2h(s[2 * kk][0],     s[2 * kk][1]);
            ph[1] = pack2h(s[2 * kk][2],     s[2 * kk][3]);
            ph[2] = pack2h(s[2 * kk + 1][0], s[2 * kk + 1][1]);
            ph[3] = pack2h(s[2 * kk + 1][2], s[2 * kk + 1][3]);
#pragma unroll
            for (int np = 0; np < 4; ++np) {
                uint32_t vh0[4], vh1[4];
                uint32_t va = su + VH_O + (c0 * 64 + kk * 16 + l16) * 272
                            + (lane >> 4) * 16 + (2 * np) * 32;
                LDMX4T(vh0, va);
                LDMX4T(vh1, va + 32);
                uint32_t bh0[2] = {vh0[0], vh0[1]}, bh1[2] = {vh0[2], vh0[3]};
                uint32_t bh2[2] = {vh1[0], vh1[1]}, bh3[2] = {vh1[2], vh1[3]};
                mma16816h(o[4 * np],     ph, bh0);
                mma16816h(o[4 * np + 1], ph, bh1);
                mma16816h(o[4 * np + 2], ph, bh2);
                mma16816h(o[4 * np + 3], ph, bh3);
            }
        }
    }

    float rin[2] = {1.f / lrow[0], 1.f / lrow[1]};
#pragma unroll
    for (int nt = 0; nt < 16; ++nt) {
        int ch = nt * 8 + (lane & 3) * 2;
#pragma unroll
        for (int h = 0; h < 2; ++h) {
            int v = q0 + (lane >> 2) + h * 8;
            size_t ad = ((size_t)(b * 256 + v) * 64 + t) * 128 + ch;
            *(uint32_t*)(avh + ad)
                = pack2h(o[nt][2 * h] * rin[h], o[nt][2 * h + 1] * rin[h]);
        }
    }
}

// ---------------------------------------------------------------------------
extern "C" void kernel_launch(void* const* d_in, const int* in_sizes, int n_in,
                              void* d_out, int out_size) {
    const float* x     = (const float*)d_in[0];
    const float* wq    = (const float*)d_in[1];
    const float* wk    = (const float*)d_in[2];
    const float* wv    = (const float*)d_in[3];
    const float* wo    = (const float*)d_in[4];
    const float* sigma = (const float*)d_in[5];
    float* out = (float*)d_out;

    __half *xh, *qkv, *avh, *w1h, *w2h;
    cudaGetSymbolAddress((void**)&xh,   g_xh);
    cudaGetSymbolAddress((void**)&qkv,  g_qkv);
    cudaGetSymbolAddress((void**)&avh,  g_avh);
    cudaGetSymbolAddress((void**)&w1h,  g_w1h);
    cudaGetSymbolAddress((void**)&w2h,  g_w2h);

    cudaFuncSetAttribute(prep_k,
                         cudaFuncAttributeMaxDynamicSharedMemorySize, 66560);
    prep_k<<<4928, 256, 66560>>>(x, wq, wk, wv, wo, xh, w1h, w2h);

    {   // conv1: IC=256 (8 x 32-ic chunks), OCTOT=192, fp16 transposed output
        auto k = conv_mma<8, 192, true>;
        cudaFuncSetAttribute(k, cudaFuncAttributeMaxDynamicSharedMemorySize,
                             CONV_SMEM);
        k<<<dim3(3, 64, 8), 256, CONV_SMEM>>>(xh, w1h,
                                              qkv, nullptr, nullptr, nullptr);
    }

    cudaFuncSetAttribute(attn_kernel,
                         cudaFuncAttributeMaxDynamicSharedMemorySize, ATTN_SMEM);
    attn_kernel<<<dim3(T_, B_), 512, ATTN_SMEM>>>(qkv, avh);

    {   // conv2: IC=128 (4 x 32-ic chunks), OCTOT=256, fp32 out + residual
        auto k = conv_mma<4, 256, false>;
        cudaFuncSetAttribute(k, cudaFuncAttributeMaxDynamicSharedMemorySize,
                             CONV_SMEM);
        k<<<dim3(4, 64, 8), 256, CONV_SMEM>>>(avh, w2h,
                                              nullptr, out, x, sigma);
    }
}

// round 15
// speedup vs baseline: 2.6971x; 1.0393x over previous
#include <cuda_runtime.h>
#include <cuda_bf16.h>
#include <cuda_fp16.h>
#include <cstdint>

#define B_   8
#define V_   256
#define T_   64

// ---------------------------------------------------------------------------
// Global scratch
// ---------------------------------------------------------------------------
__device__ __half g_xh[8ll * 256 * 64 * 256];            // [b][v][t][256ic] fp16
__device__ __half g_qkv[8ll * 64 * 256 * 192];           // [b][t][v][192] fp16
__device__ __half g_avh[8ll * 256 * 64 * 128];           // [b][v][t][128ic] fp16
__device__ __half g_w1h[192 * 2304];                     // [oc][chunk32][tap][32] fp16
__device__ __half g_w2h[256 * 1152];

// ---------------------------------------------------------------------------
// Helpers
// ---------------------------------------------------------------------------
__device__ __forceinline__ uint32_t smem_u32(const void* p) {
    return (uint32_t)__cvta_generic_to_shared(p);
}
__device__ __forceinline__ uint32_t pack2h(float f0, float f1) {
    __half2 h = __floats2half2_rn(f0, f1);
    return *(uint32_t*)&h;
}

#define LDMX4(r, a) \
    asm volatile("ldmatrix.sync.aligned.m8n8.x4.shared.b16 {%0,%1,%2,%3},[%4];" \
        : "=r"((r)[0]), "=r"((r)[1]), "=r"((r)[2]), "=r"((r)[3]) : "r"(a))
#define LDMX4T(r, a) \
    asm volatile("ldmatrix.sync.aligned.m8n8.x4.trans.shared.b16 {%0,%1,%2,%3},[%4];" \
        : "=r"((r)[0]), "=r"((r)[1]), "=r"((r)[2]), "=r"((r)[3]) : "r"(a))
#define CP16(dst, src, sz) \
    asm volatile("cp.async.cg.shared.global [%0], [%1], 16, %2;" \
                 :: "r"(dst), "l"(src), "r"(sz) : "memory")
#define CP_COMMIT() asm volatile("cp.async.commit_group;" ::: "memory")
#define CP_WAIT(n)  asm volatile("cp.async.wait_group %0;" :: "n"(n) : "memory")

__device__ __forceinline__ void mma16816h(float* c, const uint32_t* a, const uint32_t* b) {
    asm volatile(
        "mma.sync.aligned.m16n8k16.row.col.f32.f16.f16.f32 "
        "{%0,%1,%2,%3},{%4,%5,%6,%7},{%8,%9},{%0,%1,%2,%3};"
        : "+f"(c[0]), "+f"(c[1]), "+f"(c[2]), "+f"(c[3])
        : "r"(a[0]), "r"(a[1]), "r"(a[2]), "r"(a[3]), "r"(b[0]), "r"(b[1]));
}

// ---------------------------------------------------------------------------
// Merged prep kernel:
//   blocks [0, 2048):        split_x   (x NCHW fp32 -> [b][y][t][256ic] fp16)
//   blocks [2048, 3776):     pack_w1   ([oc][ic][3][3] -> [oc][chunk32][tap][32])
//   blocks [3776, 4928):     pack_w2
// ---------------------------------------------------------------------------
__global__ void prep_k(const float* __restrict__ x,
                       const float* __restrict__ wq,
                       const float* __restrict__ wk,
                       const float* __restrict__ wv,
                       const float* __restrict__ wo,
                       __half* __restrict__ xh,
                       __half* __restrict__ w1h,
                       __half* __restrict__ w2h) {
    const int bid = blockIdx.x, tid = threadIdx.x;
    if (bid < 2048) {
        extern __shared__ float s[];               // [256 ic][65]
        const int y = bid & 255, b = bid >> 8;
        for (int r = 0; r < 64; r++) {
            int idx = r * 256 + tid, ic = idx >> 6, t = idx & 63;
            s[ic * 65 + t] = x[(((size_t)b * 256 + ic) * 256 + y) * 64 + t];
        }
        __syncthreads();
        size_t ob = ((size_t)(b * 256 + y)) * 64 * 256;
        for (int r = 0; r < 32; r++) {
            int idx = r * 512 + tid * 2, t = idx >> 8, ic = idx & 255;
            *(uint32_t*)(xh + ob + (size_t)t * 256 + ic)
                = pack2h(s[ic * 65 + t], s[(ic + 1) * 65 + t]);
        }
    } else if (bid < 3776) {
        int id = (bid - 2048) * 256 + tid;          // 192*2304
        int oc = id / 2304, kp = id % 2304;
        int chunk = kp / 288, rem = kp % 288, tap = rem / 32, i = rem & 31;
        int ic = chunk * 32 + i;
        float v;
        if (oc < 32)       v = wq[(oc * 256 + ic) * 9 + tap];
        else if (oc < 64)  v = wk[((oc - 32) * 256 + ic) * 9 + tap];
        else               v = wv[((oc - 64) * 256 + ic) * 9 + tap];
        w1h[id] = __float2half_rn(v);
    } else {
        int id = (bid - 3776) * 256 + tid;          // 256*1152
        int oc = id / 1152, kp = id % 1152;
        int chunk = kp / 288, rem = kp % 288, tap = rem / 32, i = rem & 31;
        int ic = chunk * 32 + i;
        w2h[id] = __float2half_rn(wo[(oc * 128 + ic) * 9 + tap]);
    }
}

// ---------------------------------------------------------------------------
// conv3x3 via mma.sync fp16, single-pass, 32-ic chunks.
// CTA: 256 thr (8 warps: 4 m x 2 n), 2 CTAs/SM. M=256 positions x N=64 oc.
// A double-buffered, B single-buffered (cp.async).
// Patch: [6 rows][66 cols] pixels of 80B stride. B: [64 oc][592B stride].
// Epilogue stages the 256x64 output tile through smem for fully-coalesced
// float4/uint4 global stores (and float4 residual loads).
// ---------------------------------------------------------------------------
#define ABUF    31680          // one A buffer (6*66*80)
#define BH_O    63360          // B base (2*ABUF)
#define CONV_SMEM 101248       // BH_O + 64*592

template<int ICC, int OCTOT, bool TRANS>
__global__ __launch_bounds__(256, 2)
void conv_mma(const __half* __restrict__ inh,
              const __half* __restrict__ wh,
              __half* __restrict__ outh,
              float* __restrict__ out32,
              const float* __restrict__ resid,
              const float* __restrict__ sigma) {
    constexpr int IC = ICC * 32;
    extern __shared__ char sm[];

    const int tid  = threadIdx.x;
    const int lane = tid & 31;
    const int w    = tid >> 5;
    const int ocB  = blockIdx.x * 64;
    const int y0   = blockIdx.y * 4;
    const int b    = blockIdx.z;
    const int m0   = (w & 3) * 64;
    const int n0   = (w >> 2) * 32;
    const uint32_t su = smem_u32(sm);

    float acc[4][4][4];
#pragma unroll
    for (int i = 0; i < 4; i++)
#pragma unroll
        for (int j = 0; j < 4; j++)
#pragma unroll
            for (int e = 0; e < 4; e++) acc[i][j][e] = 0.f;

    auto stageA = [&](int c, int buf) {
        uint32_t au = su + buf * ABUF;
        for (int p = tid; p < 396; p += 256) {
            int row = p / 66, col = p - row * 66;
            int gy = y0 + row - 1, gt = col - 1;
            bool ok = ((unsigned)gy < 256u) && ((unsigned)gt < 64u);
            const __half* src = ok
                ? inh + ((size_t)((b * 256 + gy) * 64 + gt)) * IC + c * 32
                : inh;
            uint32_t dst = au + (uint32_t)p * 80;
            int sz = ok ? 16 : 0;
            CP16(dst,      src,      sz);
            CP16(dst + 16, src + 8,  sz);
            CP16(dst + 32, src + 16, sz);
            CP16(dst + 48, src + 24, sz);
        }
    };
    auto stageB = [&](int c) {
        for (int i = tid; i < 2304; i += 256) {
            int n = i / 36, seg = i - n * 36;
            const __half* src = wh + ((size_t)(ocB + n) * ICC + c) * 288 + seg * 8;
            uint32_t dst = su + BH_O + n * 592 + seg * 16;
            CP16(dst, src, 16);
        }
    };

    stageA(0, 0);
    CP_COMMIT();

    const int l16 = lane & 15;
    const int bg   = lane >> 3;
    const int brow = (bg >> 1) * 8 + (lane & 7);
    const int bko  = (bg & 1) * 16;

    for (int c = 0; c < ICC; ++c) {
        stageB(c);
        CP_COMMIT();
        if (c + 1 < ICC) {
            stageA(c + 1, (c + 1) & 1);
            CP_COMMIT();
            CP_WAIT(1);        // B(c)+A(c) done; A(c+1) in flight
        } else {
            CP_WAIT(0);
        }
        __syncthreads();

        const uint32_t sa = su + (c & 1) * ABUF;
        const uint32_t sb = su + BH_O;
#pragma unroll
        for (int tap = 0; tap < 9; ++tap) {
            const int ky = tap / 3, kx = tap - ky * 3;
#pragma unroll
            for (int kk = 0; kk < 2; ++kk) {
                uint32_t bf0[4], bf1[4];
                {
                    uint32_t ad = sb + (n0 + brow) * 592 + tap * 64 + kk * 32 + bko;
                    LDMX4(bf0, ad);
                    LDMX4(bf1, ad + 16 * 592);
                }
#pragma unroll
                for (int mp = 0; mp < 2; ++mp) {
                    uint32_t a0h[4], a1h[4];
                    {
                        int mrow = m0 + (2 * mp) * 16 + l16;
                        int rp = (mrow >> 6) + ky, cp = (mrow & 63) + kx;
                        uint32_t ad = sa + (uint32_t)(rp * 66 + cp) * 80
                                    + (lane >> 4) * 16 + kk * 32;
                        LDMX4(a0h, ad);
                    }
                    {
                        int mrow = m0 + (2 * mp + 1) * 16 + l16;
                        int rp = (mrow >> 6) + ky, cp = (mrow & 63) + kx;
                        uint32_t ad = sa + (uint32_t)(rp * 66 + cp) * 80
                                    + (lane >> 4) * 16 + kk * 32;
                        LDMX4(a1h, ad);
                    }
                    mma16816h(acc[2 * mp][0],     a0h, &bf0[0]);
                    mma16816h(acc[2 * mp][1],     a0h, &bf0[2]);
                    mma16816h(acc[2 * mp][2],     a0h, &bf1[0]);
                    mma16816h(acc[2 * mp][3],     a0h, &bf1[2]);
                    mma16816h(acc[2 * mp + 1][0], a1h, &bf0[0]);
                    mma16816h(acc[2 * mp + 1][1], a1h, &bf0[2]);
                    mma16816h(acc[2 * mp + 1][2], a1h, &bf1[0]);
                    mma16816h(acc[2 * mp + 1][3], a1h, &bf1[2]);
                }
            }
        }
        __syncthreads();       // protect B buffer + A buffer reuse
    }

    // ---- epilogue: stage tile [256 pos][64 oc] through smem, coalesced out ----
    const int r0l = lane >> 2, c0l = (lane & 3) * 2;
    if constexpr (TRANS) {
        // fp16-pair tile: [pos][34] uint32 (stride 34, payload 32)
        uint32_t* so = (uint32_t*)sm;
#pragma unroll
        for (int mt = 0; mt < 4; ++mt)
#pragma unroll
            for (int nt = 0; nt < 4; ++nt)
#pragma unroll
                for (int h = 0; h < 2; ++h) {
                    int m = m0 + mt * 16 + r0l + h * 8;
                    int oc2 = (n0 + nt * 8 + c0l) >> 1;
                    so[m * 34 + oc2]
                        = pack2h(acc[mt][nt][h * 2], acc[mt][nt][h * 2 + 1]);
                }
        __syncthreads();
        // write: 2048 uint4 (each = 8 oc halves); 8 lanes cover one pos (128B)
#pragma unroll
        for (int j = 0; j < 8; ++j) {
            int idx = j * 256 + tid;
            int pos = idx >> 3, seg = idx & 7;
            int v = y0 + (pos >> 6), t = pos & 63;
            uint32_t r0 = so[pos * 34 + seg * 4 + 0];
            uint32_t r1 = so[pos * 34 + seg * 4 + 1];
            uint32_t r2 = so[pos * 34 + seg * 4 + 2];
            uint32_t r3 = so[pos * 34 + seg * 4 + 3];
            size_t ad = ((size_t)((b * 64 + t) * 256 + v)) * OCTOT + ocB + seg * 8;
            *(uint4*)(outh + ad) = make_uint4(r0, r1, r2, r3);
        }
    } else {
        // fp32 tile: [pos][67] floats (stride 67, payload 64)
        float* so = (float*)sm;
#pragma unroll
        for (int mt = 0; mt < 4; ++mt)
#pragma unroll
            for (int nt = 0; nt < 4; ++nt)
#pragma unroll
                for (int h = 0; h < 2; ++h) {
                    int m = m0 + mt * 16 + r0l + h * 8;
                    int oc = n0 + nt * 8 + c0l;
                    so[m * 67 + oc]     = acc[mt][nt][h * 2];
                    so[m * 67 + oc + 1] = acc[mt][nt][h * 2 + 1];
                }
        __syncthreads();
        float sg = sigma[0];
        // write: 4096 float4; each oc has 64 float4 over 256 contiguous positions
#pragma unroll
        for (int j = 0; j < 16; ++j) {
            int idx = j * 256 + tid;
            int ocl = idx >> 6;                  // 0..63
            int mb  = (idx & 63) * 4;            // position base 0..252
            size_t ad = ((size_t)(b * OCTOT + ocB + ocl)) * 16384
                      + (size_t)y0 * 64 + mb;
            float4 r = *(const float4*)&resid[ad];
            float4 val;
            val.x = r.x + sg * so[(mb + 0) * 67 + ocl];
            val.y = r.y + sg * so[(mb + 1) * 67 + ocl];
            val.z = r.z + sg * so[(mb + 2) * 67 + ocl];
            val.w = r.w + sg * so[(mb + 3) * 67 + ocl];
            *(float4*)&out32[ad] = val;
        }
    }
}

// ---------------------------------------------------------------------------
// Attention, all-fp16 single-pass mma (flash-style online softmax, fp32 accum).
// One CTA per (b,t): 512 thr, 16 warps, warp owns 16 query rows.
// SMEM: Q [256 x 80B], K [256 x 80B], V [256 x 272B]  (fp16).
// ---------------------------------------------------------------------------
#define QH_O 0
#define KH_O 20480
#define VH_O 40960
#define ATTN_SMEM 110592

__global__ __launch_bounds__(512, 1)
void attn_kernel(const __half* __restrict__ qkv,
                 __half* __restrict__ avh) {
    extern __shared__ char smc[];
    const int tid  = threadIdx.x;
    const int lane = tid & 31;
    const int w    = tid >> 5;
    const int t    = blockIdx.x;
    const int b    = blockIdx.y;
    const uint32_t su = smem_u32(smc);

    const size_t sbase = ((size_t)(b * 64 + t)) * 256 * 192;
    for (int idx = tid; idx < 6144; idx += 512) {
        int row = idx / 24, seg = idx % 24;
        float4 val = *(const float4*)(qkv + sbase + (size_t)row * 192 + seg * 8);
        uint32_t dst;
        if (seg < 4)       dst = QH_O + row * 80 + seg * 16;
        else if (seg < 8)  dst = KH_O + row * 80 + (seg - 4) * 16;
        else               dst = VH_O + row * 272 + (seg - 8) * 16;
        *(float4*)(smc + dst) = val;
    }
    __syncthreads();

    const int q0  = w * 16;
    const int l16 = lane & 15;

    float o[16][4];
#pragma unroll
    for (int i = 0; i < 16; i++)
#pragma unroll
        for (int j = 0; j < 4; j++) o[i][j] = 0.f;
    float mrow[2] = {-1e30f, -1e30f};
    float lrow[2] = {0.f, 0.f};

    for (int c0 = 0; c0 < 4; ++c0) {
        float s[8][4];
#pragma unroll
        for (int i = 0; i < 8; i++)
#pragma unroll
            for (int j = 0; j < 4; j++) s[i][j] = 0.f;

#pragma unroll
        for (int kk = 0; kk < 2; ++kk) {
            uint32_t aH[4];
            uint32_t qa = su + QH_O + (q0 + l16) * 80 + (lane >> 4) * 16 + kk * 32;
            LDMX4(aH, qa);
#pragma unroll
            for (int np = 0; np < 2; ++np) {
                uint32_t kh0[4], kh1[4];
                uint32_t ka0 = su + KH_O + (c0 * 64 + (2 * np) * 16 + l16) * 80
                             + (lane >> 4) * 16 + kk * 32;
                LDMX4(kh0, ka0);
                LDMX4(kh1, ka0 + 16 * 80);
                uint32_t b0h[2] = {kh0[0], kh0[2]}, b1h[2] = {kh0[1], kh0[3]};
                uint32_t b2h[2] = {kh1[0], kh1[2]}, b3h[2] = {kh1[1], kh1[3]};
                mma16816h(s[4 * np],     aH, b0h);
                mma16816h(s[4 * np + 1], aH, b1h);
                mma16816h(s[4 * np + 2], aH, b2h);
                mma16816h(s[4 * np + 3], aH, b3h);
            }
        }

#pragma unroll
        for (int h = 0; h < 2; ++h) {
            float mc = -1e30f;
#pragma unroll
            for (int nt = 0; nt < 8; ++nt)
                mc = fmaxf(mc, fmaxf(s[nt][2 * h], s[nt][2 * h + 1]));
            mc = fmaxf(mc, __shfl_xor_sync(0xffffffffu, mc, 1));
            mc = fmaxf(mc, __shfl_xor_sync(0xffffffffu, mc, 2));
            float mn = fmaxf(mrow[h], mc);
            float sc = __expf(mrow[h] - mn);
            mrow[h] = mn;
            float ls = 0.f;
#pragma unroll
            for (int nt = 0; nt < 8; ++nt) {
                float p0 = __expf(s[nt][2 * h] - mn);
                float p1 = __expf(s[nt][2 * h + 1] - mn);
                s[nt][2 * h] = p0; s[nt][2 * h + 1] = p1;
                ls += p0 + p1;
            }
            ls += __shfl_xor_sync(0xffffffffu, ls, 1);
            ls += __shfl_xor_sync(0xffffffffu, ls, 2);
            lrow[h] = lrow[h] * sc + ls;
#pragma unroll
            for (int nt = 0; nt < 16; ++nt) {
                o[nt][2 * h]     *= sc;
                o[nt][2 * h + 1] *= sc;
            }
        }

#pragma unroll
        for (int kk = 0; kk < 4; ++kk) {
            uint32_t ph[4];
            ph[0] = pack2h(s[2 * kk][0],     s[2 * kk][1]);
            ph[1] = pack2h(s[2 * kk][2],     s[2 * kk][3]);
            ph[2] = pack2h(s[2 * kk + 1][0], s[2 * kk + 1][1]);
            ph[3] = pack2h(s[2 * kk + 1][2], s[2 * kk + 1][3]);
#pragma unroll
            for (int np = 0; np < 4; ++np) {
                uint32_t vh0[4], vh1[4];
                uint32_t va = su + VH_O + (c0 * 64 + kk * 16 + l16) * 272
                            + (lane >> 4) * 16 + (2 * np) * 32;
                LDMX4T(vh0, va);
                LDMX4T(vh1, va + 32);
                uint32_t bh0[2] = {vh0[0], vh0[1]}, bh1[2] = {vh0[2], vh0[3]};
                uint32_t bh2[2] = {vh1[0], vh1[1]}, bh3[2] = {vh1[2], vh1[3]};
                mma16816h(o[4 * np],     ph, bh0);
                mma16816h(o[4 * np + 1], ph, bh1);
                mma16816h(o[4 * np + 2], ph, bh2);
                mma16816h(o[4 * np + 3], ph, bh3);
            }
        }
    }

    float rin[2] = {1.f / lrow[0], 1.f / lrow[1]};
#pragma unroll
    for (int nt = 0; nt < 16; ++nt) {
        int ch = nt * 8 + (lane & 3) * 2;
#pragma unroll
        for (int h = 0; h < 2; ++h) {
            int v = q0 + (lane >> 2) + h * 8;
            size_t ad = ((size_t)(b * 256 + v) * 64 + t) * 128 + ch;
            *(uint32_t*)(avh + ad)
                = pack2h(o[nt][2 * h] * rin[h], o[nt][2 * h + 1] * rin[h]);
        }
    }
}

// ---------------------------------------------------------------------------
extern "C" void kernel_launch(void* const* d_in, const int* in_sizes, int n_in,
                              void* d_out, int out_size) {
    const float* x     = (const float*)d_in[0];
    const float* wq    = (const float*)d_in[1];
    const float* wk    = (const float*)d_in[2];
    const float* wv    = (const float*)d_in[3];
    const float* wo    = (const float*)d_in[4];
    const float* sigma = (const float*)d_in[5];
    float* out = (float*)d_out;

    __half *xh, *qkv, *avh, *w1h, *w2h;
    cudaGetSymbolAddress((void**)&xh,   g_xh);
    cudaGetSymbolAddress((void**)&qkv,  g_qkv);
    cudaGetSymbolAddress((void**)&avh,  g_avh);
    cudaGetSymbolAddress((void**)&w1h,  g_w1h);
    cudaGetSymbolAddress((void**)&w2h,  g_w2h);

    cudaFuncSetAttribute(prep_k,
                         cudaFuncAttributeMaxDynamicSharedMemorySize, 66560);
    prep_k<<<4928, 256, 66560>>>(x, wq, wk, wv, wo, xh, w1h, w2h);

    {   // conv1: IC=256 (8 x 32-ic chunks), OCTOT=192, fp16 transposed output
        auto k = conv_mma<8, 192, true>;
        cudaFuncSetAttribute(k, cudaFuncAttributeMaxDynamicSharedMemorySize,
                             CONV_SMEM);
        k<<<dim3(3, 64, 8), 256, CONV_SMEM>>>(xh, w1h,
                                              qkv, nullptr, nullptr, nullptr);
    }

    cudaFuncSetAttribute(attn_kernel,
                         cudaFuncAttributeMaxDynamicSharedMemorySize, ATTN_SMEM);
    attn_kernel<<<dim3(T_, B_), 512, ATTN_SMEM>>>(qkv, avh);

    {   // conv2: IC=128 (4 x 32-ic chunks), OCTOT=256, fp32 out + residual
        auto k = conv_mma<4, 256, false>;
        cudaFuncSetAttribute(k, cudaFuncAttributeMaxDynamicSharedMemorySize,
                             CONV_SMEM);
        k<<<dim3(4, 64, 8), 256, CONV_SMEM>>>(avh, w2h,
                                              nullptr, out, x, sigma);
    }
}